// round 1
// baseline (speedup 1.0000x reference)
#include <cuda_runtime.h>

// MiniEmbedding: per-window kNN (K=128 pts, 16 NN) -> center+scale-normalize
// -> MLP 3->32->64->128 (relu, relu, linear) -> max over 16 neighbors.
// windows: (1024,128,3) f32. out: (1024,128,128) f32.
//
// Layout: block = 256 threads handles 16 query points of one window.
//   grid = M*8 blocks. Each warp covers 2 points; each 16-lane half-warp
//   covers the 16 neighbors of one point (one lane == one neighbor row).
//   h1[32], h2[64] live in registers; weights in SMEM (broadcast loads).
//   Layer-3 output max over neighbors via xor-shuffle butterfly per 16 lanes.

#define NTHREADS 256

__global__ void __launch_bounds__(NTHREADS, 1)
mini_embedding_kernel(const float* __restrict__ windows,
                      const float* __restrict__ W1, const float* __restrict__ b1,
                      const float* __restrict__ W2, const float* __restrict__ b2,
                      const float* __restrict__ W3, const float* __restrict__ b3,
                      float* __restrict__ out)
{
    __shared__ float px[128], py[128], pz[128], sqn[128];
    __shared__ float sW1[3][32], sb1[32];
    __shared__ float sW2[32][64], sb2[64];
    __shared__ float sW3[64][128], sb3[128];
    __shared__ float d2row[16][128];

    const int tid = threadIdx.x;
    const int m   = blockIdx.x >> 3;   // window index
    const int grp = blockIdx.x & 7;    // 16-point group within the window

    // ---- cooperative loads: points (+ squared norms) and weights ----
    const float* wptr = windows + (size_t)m * 128 * 3;
    for (int i = tid; i < 128; i += NTHREADS) {
        float x = wptr[i * 3 + 0];
        float y = wptr[i * 3 + 1];
        float z = wptr[i * 3 + 2];
        px[i] = x; py[i] = y; pz[i] = z;
        sqn[i] = x * x + y * y + z * z;
    }
    for (int i = tid; i < 96;   i += NTHREADS) sW1[i / 32][i % 32]  = W1[i];
    for (int i = tid; i < 32;   i += NTHREADS) sb1[i] = b1[i];
    for (int i = tid; i < 2048; i += NTHREADS) sW2[i / 64][i % 64]  = W2[i];
    for (int i = tid; i < 64;   i += NTHREADS) sb2[i] = b2[i];
    for (int i = tid; i < 8192; i += NTHREADS) sW3[i / 128][i % 128] = W3[i];
    for (int i = tid; i < 128;  i += NTHREADS) sb3[i] = b3[i];
    __syncthreads();

    // ---- pairwise squared distances for our 16 query points ----
    {
        const int q  = tid >> 4;          // local query 0..15
        const int jb = (tid & 15) * 8;    // 8 candidates per thread
        const int qg = grp * 16 + q;
        const float qx = px[qg], qy = py[qg], qz = pz[qg], sq = sqn[qg];
        #pragma unroll
        for (int j = jb; j < jb + 8; ++j) {
            float dot = qx * px[j] + qy * py[j] + qz * pz[j];
            d2row[q][j] = sq + sqn[j] - 2.0f * dot;
        }
    }
    __syncthreads();

    // ---- per-thread identity for selection + MLP ----
    const int lane = tid & 31;
    const int n    = lane & 15;                      // neighbor slot 0..15
    const int pl   = (tid >> 5) * 2 + (lane >> 4);   // local point 0..15
    const int pg   = grp * 16 + pl;                  // point within window

    // ---- top-16 nearest selection (16 rounds of cooperative argmin) ----
    // Tie-break: smaller index first == jax.lax.top_k stability on -d2.
    float myv[8];
    const int jb = n * 8;
    #pragma unroll
    for (int i = 0; i < 8; ++i) myv[i] = d2row[pl][jb + i];

    unsigned msk = 0xFFu;
    int myIdx = 0;
    for (int r = 0; r < 16; ++r) {
        float bv = 3.4e38f;
        int   bj = 1 << 30;
        #pragma unroll
        for (int i = 0; i < 8; ++i) {
            if ((msk >> i) & 1u) {
                float v = myv[i];
                if (v < bv) { bv = v; bj = jb + i; }   // ascending i keeps min idx on ties
            }
        }
        #pragma unroll
        for (int s = 1; s < 16; s <<= 1) {
            float ov = __shfl_xor_sync(0xffffffffu, bv, s, 16);
            int   oj = __shfl_xor_sync(0xffffffffu, bj, s, 16);
            if (ov < bv || (ov == bv && oj < bj)) { bv = ov; bj = oj; }
        }
        if (r == n) myIdx = bj;                        // slot n owns the r-th nearest
        if (bj >= jb && bj < jb + 8) msk &= ~(1u << (bj - jb));
    }

    // ---- relative coords + neighborhood scale normalization ----
    float rx = px[myIdx] - px[pg];
    float ry = py[myIdx] - py[pg];
    float rz = pz[myIdx] - pz[pg];
    float n2 = rx * rx + ry * ry + rz * rz;
    float mx = n2;
    #pragma unroll
    for (int s = 1; s < 16; s <<= 1)
        mx = fmaxf(mx, __shfl_xor_sync(0xffffffffu, mx, s, 16));
    float scale = sqrtf(mx);                 // sqrt(max n2) == max(sqrt n2) exactly
    float invd  = 1.0f / fmaxf(scale, 1e-8f);
    rx *= invd; ry *= invd; rz *= invd;

    // ---- layer 1: 3 -> 32, relu ----
    float h1[32];
    #pragma unroll
    for (int o = 0; o < 32; ++o) {
        float a = sb1[o] + rx * sW1[0][o] + ry * sW1[1][o] + rz * sW1[2][o];
        h1[o] = fmaxf(a, 0.0f);
    }

    // ---- layer 2: 32 -> 64, relu (h2 in registers) ----
    float h2[64];
    #pragma unroll
    for (int o = 0; o < 64; o += 4) {
        float a0 = sb2[o], a1 = sb2[o + 1], a2 = sb2[o + 2], a3 = sb2[o + 3];
        #pragma unroll
        for (int k = 0; k < 32; ++k) {
            const float hk = h1[k];
            const float4 w = *(const float4*)&sW2[k][o];
            a0 += hk * w.x; a1 += hk * w.y; a2 += hk * w.z; a3 += hk * w.w;
        }
        h2[o]     = fmaxf(a0, 0.0f);
        h2[o + 1] = fmaxf(a1, 0.0f);
        h2[o + 2] = fmaxf(a2, 0.0f);
        h2[o + 3] = fmaxf(a3, 0.0f);
    }

    // ---- layer 3: 64 -> 128 linear, then max over the 16 neighbor lanes ----
    const size_t outBase = ((size_t)m * 128 + pg) * 128;
    #pragma unroll 1
    for (int cc = 0; cc < 128; cc += 16) {
        float acc[16];
        #pragma unroll
        for (int c = 0; c < 16; ++c) acc[c] = sb3[cc + c];
        #pragma unroll
        for (int k = 0; k < 64; ++k) {
            const float hk = h2[k];
            #pragma unroll
            for (int c4 = 0; c4 < 16; c4 += 4) {
                const float4 w = *(const float4*)&sW3[k][cc + c4];
                acc[c4 + 0] += hk * w.x;
                acc[c4 + 1] += hk * w.y;
                acc[c4 + 2] += hk * w.z;
                acc[c4 + 3] += hk * w.w;
            }
        }
        // butterfly max across the 16 neighbor lanes for each column
        #pragma unroll
        for (int c = 0; c < 16; ++c) {
            #pragma unroll
            for (int s = 1; s < 16; s <<= 1)
                acc[c] = fmaxf(acc[c], __shfl_xor_sync(0xffffffffu, acc[c], s, 16));
        }
        // lane n writes column cc+n (static-index select to avoid local-mem)
        float res = acc[0];
        #pragma unroll
        for (int c = 1; c < 16; ++c)
            if (c == n) res = acc[c];
        out[outBase + cc + n] = res;
    }
}

extern "C" void kernel_launch(void* const* d_in, const int* in_sizes, int n_in,
                              void* d_out, int out_size)
{
    const float* windows = (const float*)d_in[0];
    const float* W1 = (const float*)d_in[1];
    const float* b1 = (const float*)d_in[2];
    const float* W2 = (const float*)d_in[3];
    const float* b2 = (const float*)d_in[4];
    const float* W3 = (const float*)d_in[5];
    const float* b3 = (const float*)d_in[6];
    float* out = (float*)d_out;

    const int M = in_sizes[0] / (128 * 3);   // number of windows
    dim3 grid(M * 8);
    dim3 block(NTHREADS);
    mini_embedding_kernel<<<grid, block>>>(windows, W1, b1, W2, b2, W3, b3, out);
}

// round 2
// speedup vs baseline: 1.4287x; 1.4287x over previous
#include <cuda_runtime.h>

typedef unsigned long long ull;

#define NTHREADS 256

// ---- dynamic shared memory layout (bytes) ----
// union region: first used as d2[32][128] f32 (16384 B), later as sred[256][17] ull (34816 B)
#define OFF_UNION 0
#define OFF_PX    34816
#define OFF_PY    (OFF_PX + 512)
#define OFF_PZ    (OFF_PY + 512)
#define OFF_SQ    (OFF_PZ + 512)
#define OFF_W1    (OFF_SQ + 512)      // 3*32*4   = 384
#define OFF_B1    (OFF_W1 + 384)      // 32*4     = 128
#define OFF_W2    (OFF_B1 + 128)      // 32*64*4  = 8192
#define OFF_B2    (OFF_W2 + 8192)     // 64*4     = 256
#define OFF_W3    (OFF_B2 + 256)      // 64*128*4 = 32768 (16B aligned: 45824)
#define OFF_B3    (OFF_W3 + 32768)    // 128*4    = 512
#define SMEM_TOTAL (OFF_B3 + 512)     // 79104 bytes

// ---- packed f32x2 helpers (Blackwell FFMA2 path) ----
__device__ __forceinline__ ull dup2(float x) {
    ull r;
    asm("mov.b64 %0, {%1, %1};" : "=l"(r) : "f"(x));
    return r;
}
__device__ __forceinline__ void fma2(ull& d, ull a, ull b) {
    asm("fma.rn.f32x2 %0, %1, %2, %3;" : "=l"(d) : "l"(a), "l"(b), "l"(d));
}
__device__ __forceinline__ ull max2(ull a, ull b) {
    float al, ah, bl, bh;
    asm("mov.b64 {%0, %1}, %2;" : "=f"(al), "=f"(ah) : "l"(a));
    asm("mov.b64 {%0, %1}, %2;" : "=f"(bl), "=f"(bh) : "l"(b));
    al = fmaxf(al, bl); ah = fmaxf(ah, bh);
    ull r;
    asm("mov.b64 %0, {%1, %2};" : "=l"(r) : "f"(al), "f"(ah));
    return r;
}
__device__ __forceinline__ void unpack2(ull v, float& lo, float& hi) {
    asm("mov.b64 {%0, %1}, %2;" : "=f"(lo), "=f"(hi) : "l"(v));
}

__global__ void __launch_bounds__(NTHREADS, 1)
mini_embedding_kernel(const float* __restrict__ windows,
                      const float* __restrict__ W1, const float* __restrict__ b1,
                      const float* __restrict__ W2, const float* __restrict__ b2,
                      const float* __restrict__ W3, const float* __restrict__ b3,
                      float* __restrict__ out)
{
    extern __shared__ unsigned char smraw[];
    float (*d2)[128]   = (float(*)[128])(smraw + OFF_UNION);
    ull   (*sred)[17]  = (ull(*)[17])  (smraw + OFF_UNION);
    float* px  = (float*)(smraw + OFF_PX);
    float* py  = (float*)(smraw + OFF_PY);
    float* pz  = (float*)(smraw + OFF_PZ);
    float* sqn = (float*)(smraw + OFF_SQ);
    float (*sW1)[32]  = (float(*)[32]) (smraw + OFF_W1);
    float* sb1 = (float*)(smraw + OFF_B1);
    float (*sW2)[64]  = (float(*)[64]) (smraw + OFF_W2);
    float* sb2 = (float*)(smraw + OFF_B2);
    float (*sW3)[128] = (float(*)[128])(smraw + OFF_W3);
    float* sb3 = (float*)(smraw + OFF_B3);

    const int tid = threadIdx.x;
    const int m   = blockIdx.x >> 2;   // window
    const int grp = blockIdx.x & 3;    // group of 32 points within the window

    // ---- cooperative loads ----
    const float* wptr = windows + (size_t)m * 128 * 3;
    for (int i = tid; i < 128; i += NTHREADS) {
        float x = wptr[i * 3 + 0];
        float y = wptr[i * 3 + 1];
        float z = wptr[i * 3 + 2];
        px[i] = x; py[i] = y; pz[i] = z;
        sqn[i] = x * x + y * y + z * z;
    }
    for (int i = tid; i < 96;   i += NTHREADS) sW1[i / 32][i % 32]   = W1[i];
    for (int i = tid; i < 32;   i += NTHREADS) sb1[i] = b1[i];
    for (int i = tid; i < 2048; i += NTHREADS) sW2[i / 64][i % 64]   = W2[i];
    for (int i = tid; i < 64;   i += NTHREADS) sb2[i] = b2[i];
    for (int i = tid; i < 8192; i += NTHREADS) sW3[i / 128][i % 128] = W3[i];
    for (int i = tid; i < 128;  i += NTHREADS) sb3[i] = b3[i];
    __syncthreads();

    // ---- pairwise squared distances for our 32 query points ----
    {
        const int q  = tid >> 3;          // local query 0..31
        const int c0 = (tid & 7) * 16;    // 16 candidates per thread
        const int qg = grp * 32 + q;
        const float qx = px[qg], qy = py[qg], qz = pz[qg], sq = sqn[qg];
        #pragma unroll
        for (int j = c0; j < c0 + 16; ++j) {
            float dot = qx * px[j] + qy * py[j] + qz * pz[j];
            d2[q][j] = sq + sqn[j] - 2.0f * dot;
        }
    }
    __syncthreads();

    // ---- per-thread identity ----
    const int lane   = tid & 31;
    const int n      = lane & 15;                 // neighbor slot 0..15
    const int half   = lane >> 4;
    const int wrp    = tid >> 5;
    const int lpBase = wrp * 4 + half * 2;        // local point base; this lane serves points lpBase, lpBase+1

    // ---- kNN top-16 selection + normalize, for both points (s=0,1) ----
    float rxs[2], rys[2], rzs[2];
    #pragma unroll 1
    for (int s = 0; s < 2; ++s) {
        const int lp = lpBase + s;
        const int pg = grp * 32 + lp;

        float myv[8];
        const int jb = n * 8;
        #pragma unroll
        for (int i = 0; i < 8; ++i) myv[i] = d2[lp][jb + i];

        unsigned msk = 0xFFu;
        int myIdx = 0;
        for (int r = 0; r < 16; ++r) {
            float bv = 3.4e38f;
            int   bj = 1 << 30;
            #pragma unroll
            for (int i = 0; i < 8; ++i) {
                if ((msk >> i) & 1u) {
                    float v = myv[i];
                    if (v < bv) { bv = v; bj = jb + i; }
                }
            }
            #pragma unroll
            for (int st = 1; st < 16; st <<= 1) {
                float ov = __shfl_xor_sync(0xffffffffu, bv, st, 16);
                int   oj = __shfl_xor_sync(0xffffffffu, bj, st, 16);
                if (ov < bv || (ov == bv && oj < bj)) { bv = ov; bj = oj; }
            }
            if (r == n) myIdx = bj;
            if (bj >= jb && bj < jb + 8) msk &= ~(1u << (bj - jb));
        }

        float rx = px[myIdx] - px[pg];
        float ry = py[myIdx] - py[pg];
        float rz = pz[myIdx] - pz[pg];
        float n2 = rx * rx + ry * ry + rz * rz;
        float mx = n2;
        #pragma unroll
        for (int st = 1; st < 16; st <<= 1)
            mx = fmaxf(mx, __shfl_xor_sync(0xffffffffu, mx, st, 16));
        float invd = 1.0f / fmaxf(sqrtf(mx), 1e-8f);
        rxs[s] = rx * invd; rys[s] = ry * invd; rzs[s] = rz * invd;
    }
    __syncthreads();   // all d2 reads done; union region becomes sred

    // ---- layer 1: 3 -> 32, relu (scalar, tiny) ----
    float h1a[32], h1b[32];
    {
        const float axA = rxs[0], ayA = rys[0], azA = rzs[0];
        const float axB = rxs[1], ayB = rys[1], azB = rzs[1];
        #pragma unroll
        for (int o = 0; o < 32; ++o) {
            const float w0 = sW1[0][o], w1 = sW1[1][o], w2 = sW1[2][o], bb = sb1[o];
            h1a[o] = fmaxf(bb + axA * w0 + ayA * w1 + azA * w2, 0.0f);
            h1b[o] = fmaxf(bb + axB * w0 + ayB * w1 + azB * w2, 0.0f);
        }
    }

    // ---- layer 2: 32 -> 64, relu (f32x2 packed over column pairs, 2 rows) ----
    float h2a[64], h2b[64];
    #pragma unroll 1
    for (int ob = 0; ob < 64; ob += 16) {
        ull aA[8], aB[8];
        #pragma unroll
        for (int p = 0; p < 8; ++p) {
            ull bb = *(const ull*)&sb2[ob + 2 * p];
            aA[p] = bb; aB[p] = bb;
        }
        #pragma unroll 4
        for (int k = 0; k < 32; ++k) {
            const ull ha = dup2(h1a[k]);
            const ull hb = dup2(h1b[k]);
            const ulonglong2* wp = (const ulonglong2*)&sW2[k][ob];
            #pragma unroll
            for (int t = 0; t < 4; ++t) {
                ulonglong2 ww = wp[t];
                fma2(aA[2 * t],     ha, ww.x);
                fma2(aA[2 * t + 1], ha, ww.y);
                fma2(aB[2 * t],     hb, ww.x);
                fma2(aB[2 * t + 1], hb, ww.y);
            }
        }
        #pragma unroll
        for (int p = 0; p < 8; ++p) {
            float lo, hi;
            unpack2(aA[p], lo, hi);
            h2a[ob + 2 * p]     = fmaxf(lo, 0.0f);
            h2a[ob + 2 * p + 1] = fmaxf(hi, 0.0f);
            unpack2(aB[p], lo, hi);
            h2b[ob + 2 * p]     = fmaxf(lo, 0.0f);
            h2b[ob + 2 * p + 1] = fmaxf(hi, 0.0f);
        }
    }

    // ---- layer 3: 64 -> 128 linear (packed), staged neighbor-max, store ----
    const int hb0  = tid & ~15;           // first thread of my half-warp group
    const int rrow = n >> 3;              // 0 -> point A, 1 -> point B
    const int rp   = n & 7;               // col-pair index within 16-col block
    const size_t outRow = ((size_t)m * 128 + (grp * 32 + lpBase + rrow)) * 128;

    #pragma unroll 1
    for (int cc = 0; cc < 128; cc += 16) {
        ull aA[8], aB[8];
        #pragma unroll
        for (int p = 0; p < 8; ++p) {
            ull bb = *(const ull*)&sb3[cc + 2 * p];
            aA[p] = bb; aB[p] = bb;
        }
        #pragma unroll 4
        for (int k = 0; k < 64; ++k) {
            const ull ha = dup2(h2a[k]);
            const ull hbp = dup2(h2b[k]);
            const ulonglong2* wp = (const ulonglong2*)&sW3[k][cc];
            #pragma unroll
            for (int t = 0; t < 4; ++t) {
                ulonglong2 ww = wp[t];
                fma2(aA[2 * t],     ha,  ww.x);
                fma2(aA[2 * t + 1], ha,  ww.y);
                fma2(aB[2 * t],     hbp, ww.x);
                fma2(aB[2 * t + 1], hbp, ww.y);
            }
        }
        // stage to shared: 8 pairs of row A then 8 pairs of row B
        #pragma unroll
        for (int p = 0; p < 8; ++p) {
            sred[tid][p]     = aA[p];
            sred[tid][8 + p] = aB[p];
        }
        __syncwarp();
        // each lane reduces one (row, col-pair) over the 16 neighbor threads
        const int ri = rrow * 8 + rp;
        ull red = sred[hb0][ri];
        #pragma unroll
        for (int j = 1; j < 16; ++j)
            red = max2(red, sred[hb0 + j][ri]);
        *(ull*)&out[outRow + cc + 2 * rp] = red;
        __syncwarp();
    }
}

extern "C" void kernel_launch(void* const* d_in, const int* in_sizes, int n_in,
                              void* d_out, int out_size)
{
    const float* windows = (const float*)d_in[0];
    const float* W1 = (const float*)d_in[1];
    const float* b1 = (const float*)d_in[2];
    const float* W2 = (const float*)d_in[3];
    const float* b2 = (const float*)d_in[4];
    const float* W3 = (const float*)d_in[5];
    const float* b3 = (const float*)d_in[6];
    float* out = (float*)d_out;

    cudaFuncSetAttribute(mini_embedding_kernel,
                         cudaFuncAttributeMaxDynamicSharedMemorySize, SMEM_TOTAL);

    const int M = in_sizes[0] / (128 * 3);   // number of windows
    dim3 grid(M * 4);
    dim3 block(NTHREADS);
    mini_embedding_kernel<<<grid, block, SMEM_TOTAL>>>(windows, W1, b1, W2, b2, W3, b3, out);
}

// round 4
// speedup vs baseline: 3.4145x; 2.3899x over previous
#include <cuda_runtime.h>
#include <cstdint>

typedef unsigned long long ull;
typedef unsigned int uint;

#define NT 256

// ---------------- dynamic smem layout (bytes) ----------------
#define OFF_PX   0
#define OFF_PY   512
#define OFF_PZ   1024
#define OFF_SQ   1536
#define OFF_W1   2048                 // 3*32*4 = 384
#define OFF_B1   2432                 // 128
#define OFF_B2   2560                 // 256
#define OFF_B3   2816                 // 512
#define OFF_W2P  3328                 // float2[64][20]  = 10240
#define OFF_W3P  13568                // float2[128][36] = 36864
#define OFF_RELX 50432                // 128*16*4 = 8192
#define OFF_RELY 58624
#define OFF_RELZ 66816                // ends 75008
#define OFF_C2S  75008                // 8 warps * 32*68*4 = 8*8704 = 69632
#define SMEM_TOTAL 144640

// f32 -> tf32 (round-to-nearest), result as u32 bits / as float
__device__ __forceinline__ uint tf32u(float x) {
    uint r;
    asm("cvt.rna.tf32.f32 %0, %1;" : "=r"(r) : "f"(x));
    return r;
}
__device__ __forceinline__ float tf32f(float x) { return __uint_as_float(tf32u(x)); }

// mma m16n8k8 tf32: D += A*B ; C/D f32x4 in-place, A u32x4, B u32x2
__device__ __forceinline__ void mma8(float c[4], const uint a[4], float2 bf) {
    uint b0 = __float_as_uint(bf.x), b1 = __float_as_uint(bf.y);
    asm volatile(
        "mma.sync.aligned.m16n8k8.row.col.f32.tf32.tf32.f32 "
        "{%0,%1,%2,%3}, {%4,%5,%6,%7}, {%8,%9}, {%0,%1,%2,%3};"
        : "+f"(c[0]), "+f"(c[1]), "+f"(c[2]), "+f"(c[3])
        : "r"(a[0]), "r"(a[1]), "r"(a[2]), "r"(a[3]), "r"(b0), "r"(b1));
}
__device__ __forceinline__ ull pack2(float lo, float hi) {
    ull r;
    asm("mov.b64 %0, {%1, %2};" : "=l"(r) : "f"(lo), "f"(hi));
    return r;
}
__device__ __forceinline__ void unpk2(ull v, float& lo, float& hi) {
    asm("mov.b64 {%0, %1}, %2;" : "=f"(lo), "=f"(hi) : "l"(v));
}
__device__ __forceinline__ ull max2(ull a, ull b) {
    float al, ah, bl, bh;
    unpk2(a, al, ah); unpk2(b, bl, bh);
    return pack2(fmaxf(al, bl), fmaxf(ah, bh));
}

__global__ void __launch_bounds__(NT, 1)
mini_embedding_mma(const float* __restrict__ windows,
                   const float* __restrict__ W1, const float* __restrict__ b1,
                   const float* __restrict__ W2, const float* __restrict__ b2,
                   const float* __restrict__ W3, const float* __restrict__ b3,
                   float* __restrict__ out)
{
    extern __shared__ unsigned char smraw[];
    float* px  = (float*)(smraw + OFF_PX);
    float* py  = (float*)(smraw + OFF_PY);
    float* pz  = (float*)(smraw + OFF_PZ);
    float* sqn = (float*)(smraw + OFF_SQ);
    float* sW1 = (float*)(smraw + OFF_W1);   // [3][32]
    float* sb1 = (float*)(smraw + OFF_B1);
    float* sb2 = (float*)(smraw + OFF_B2);
    float* sb3 = (float*)(smraw + OFF_B3);
    float2* w2p = (float2*)(smraw + OFF_W2P);  // [n][20], n<64, j=kt*4+tg<16
    float2* w3p = (float2*)(smraw + OFF_W3P);  // [n][36], n<128, j=kt*4+tg<32
    float* relx = (float*)(smraw + OFF_RELX);
    float* rely = (float*)(smraw + OFF_RELY);
    float* relz = (float*)(smraw + OFF_RELZ);

    const int tid  = threadIdx.x;
    const int w    = tid >> 5;
    const int lane = tid & 31;
    const int g    = lane >> 2;   // group 0..7
    const int tg   = lane & 3;    // thread-in-group 0..3
    const int m    = blockIdx.x;

    float* c2s = (float*)(smraw + OFF_C2S) + w * (32 * 68);

    // ---- cooperative prep: points + weights (tf32-paired) ----
    const float* wptr = windows + (size_t)m * 128 * 3;
    for (int i = tid; i < 128; i += NT) {
        float x = wptr[i*3+0], y = wptr[i*3+1], z = wptr[i*3+2];
        px[i] = x; py[i] = y; pz[i] = z;
        sqn[i] = x*x + y*y + z*z;
    }
    for (int i = tid; i < 96;  i += NT) sW1[i] = W1[i];
    for (int i = tid; i < 32;  i += NT) sb1[i] = b1[i];
    for (int i = tid; i < 64;  i += NT) sb2[i] = b2[i];
    for (int i = tid; i < 128; i += NT) sb3[i] = b3[i];
    // W2p[n][kt*4+t] = (tf32(W2[kt*8+t][n]), tf32(W2[kt*8+t+4][n]))
    for (int i = tid; i < 1024; i += NT) {
        int n = i >> 4, j = i & 15, kt = j >> 2, t = j & 3;
        w2p[n*20 + j] = make_float2(tf32f(W2[(kt*8+t)*64 + n]),
                                    tf32f(W2[(kt*8+t+4)*64 + n]));
    }
    // W3p[n][kt*4+t] = (tf32(W3[kt*8+t][n]), tf32(W3[kt*8+t+4][n]))
    for (int i = tid; i < 4096; i += NT) {
        int n = i >> 5, j = i & 31, kt = j >> 2, t = j & 3;
        w3p[n*36 + j] = make_float2(tf32f(W3[(kt*8+t)*128 + n]),
                                    tf32f(W3[(kt*8+t+4)*128 + n]));
    }
    __syncthreads();

    // ---- warp-local kNN + normalize for this warp's 16 points ----
    const int half = lane >> 4;
    const int n16  = lane & 15;
    #pragma unroll 1
    for (int i4 = 0; i4 < 4; ++i4) {
        #pragma unroll 1
        for (int s = 0; s < 2; ++s) {
            const int q = 16*w + 4*i4 + 2*half + s;
            const float qx = px[q], qy = py[q], qz = pz[q], sq = sqn[q];
            float myv[8];
            const int jb = n16 * 8;
            #pragma unroll
            for (int ii = 0; ii < 8; ++ii) {
                int j = jb + ii;
                float dot = qx*px[j] + qy*py[j] + qz*pz[j];
                myv[ii] = sq + sqn[j] - 2.0f*dot;
            }
            unsigned msk = 0xFFu;
            int myIdx = 0;
            for (int r = 0; r < 16; ++r) {
                float bv = 3.4e38f; int bj = 1 << 30;
                #pragma unroll
                for (int ii = 0; ii < 8; ++ii)
                    if ((msk >> ii) & 1u) { float v = myv[ii]; if (v < bv) { bv = v; bj = jb + ii; } }
                #pragma unroll
                for (int st = 1; st < 16; st <<= 1) {
                    float ov = __shfl_xor_sync(0xffffffffu, bv, st, 16);
                    int   oj = __shfl_xor_sync(0xffffffffu, bj, st, 16);
                    if (ov < bv || (ov == bv && oj < bj)) { bv = ov; bj = oj; }
                }
                if (r == n16) myIdx = bj;
                if (bj >= jb && bj < jb + 8) msk &= ~(1u << (bj - jb));
            }
            float rx = px[myIdx] - qx;
            float ry = py[myIdx] - qy;
            float rz = pz[myIdx] - qz;
            float n2 = rx*rx + ry*ry + rz*rz;
            float mx = n2;
            #pragma unroll
            for (int st = 1; st < 16; st <<= 1)
                mx = fmaxf(mx, __shfl_xor_sync(0xffffffffu, mx, st, 16));
            float invd = 1.0f / fmaxf(sqrtf(mx), 1e-8f);
            relx[q*16 + n16] = rx * invd;
            rely[q*16 + n16] = ry * invd;
            relz[q*16 + n16] = rz * invd;
        }
    }
    __syncwarp();

    // ---- per-chunk GEMM pipeline: 8 chunks of (2 points x 16 neighbors) ----
    #pragma unroll 1
    for (int ch = 0; ch < 8; ++ch) {
        const int pA = 16*w + 2*ch;      // m-tile 0
        const int pB = pA + 1;           // m-tile 1

        // rel for my 4 rows: (pA,g),(pA,g+8),(pB,g),(pB,g+8)
        float rX[4], rY[4], rZ[4];
        rX[0] = relx[pA*16+g];   rY[0] = rely[pA*16+g];   rZ[0] = relz[pA*16+g];
        rX[1] = relx[pA*16+g+8]; rY[1] = rely[pA*16+g+8]; rZ[1] = relz[pA*16+g+8];
        rX[2] = relx[pB*16+g];   rY[2] = rely[pB*16+g];   rZ[2] = relz[pB*16+g];
        rX[3] = relx[pB*16+g+8]; rY[3] = rely[pB*16+g+8]; rZ[3] = relz[pB*16+g+8];

        // h1 in A-fragment layout: afrag[m][kt][{a0..a3}]
        uint afrag[2][4][4];
        #pragma unroll
        for (int j = 0; j < 8; ++j) {
            const int col = tg + 4*j;
            const float w0 = sW1[col], w1 = sW1[32+col], w2 = sW1[64+col], bb = sb1[col];
            const int kt = j >> 1, hi = j & 1;  // a0/a1 for hi=0, a2/a3 for hi=1
            #pragma unroll
            for (int mm = 0; mm < 2; ++mm) {
                float hg  = fmaxf(bb + rX[2*mm+0]*w0 + rY[2*mm+0]*w1 + rZ[2*mm+0]*w2, 0.0f);
                float hg8 = fmaxf(bb + rX[2*mm+1]*w0 + rY[2*mm+1]*w1 + rZ[2*mm+1]*w2, 0.0f);
                afrag[mm][kt][hi*2+0] = tf32u(hg);
                afrag[mm][kt][hi*2+1] = tf32u(hg8);
            }
        }

        // layer 2: C2(32x64) = h1(32x32) @ W2
        float c2[2][8][4];
        #pragma unroll
        for (int nt = 0; nt < 8; ++nt)
            #pragma unroll
            for (int r = 0; r < 4; ++r) { c2[0][nt][r] = 0.0f; c2[1][nt][r] = 0.0f; }
        #pragma unroll
        for (int kt = 0; kt < 4; ++kt) {
            #pragma unroll
            for (int nt = 0; nt < 8; ++nt) {
                float2 bf = w2p[(nt*8+g)*20 + kt*4 + tg];
                mma8(c2[0][nt], afrag[0][kt], bf);
                mma8(c2[1][nt], afrag[1][kt], bf);
            }
        }

        // epilogue: relu(+b2), tf32 round, stage to per-warp smem (pad 68)
        #pragma unroll
        for (int mm = 0; mm < 2; ++mm) {
            #pragma unroll
            for (int nt = 0; nt < 8; ++nt) {
                const int col = nt*8 + 2*tg;
                const float b20 = sb2[col], b21 = sb2[col+1];
                float v0 = fmaxf(c2[mm][nt][0] + b20, 0.0f);
                float v1 = fmaxf(c2[mm][nt][1] + b21, 0.0f);
                float v2 = fmaxf(c2[mm][nt][2] + b20, 0.0f);
                float v3 = fmaxf(c2[mm][nt][3] + b21, 0.0f);
                *(float2*)&c2s[(g + 16*mm)*68 + col]     = make_float2(tf32f(v0), tf32f(v1));
                *(float2*)&c2s[(g + 8 + 16*mm)*68 + col] = make_float2(tf32f(v2), tf32f(v3));
            }
        }
        __syncwarp();

        // layer 3: C3(32x128) = C2'(32x64) @ W3, two 64-col passes
        const size_t rbA = ((size_t)(m*128 + pA)) * 128;
        const size_t rbB = ((size_t)(m*128 + pB)) * 128;
        #pragma unroll 1
        for (int pp = 0; pp < 2; ++pp) {
            float c3[2][8][4];
            #pragma unroll
            for (int nt = 0; nt < 8; ++nt)
                #pragma unroll
                for (int r = 0; r < 4; ++r) { c3[0][nt][r] = 0.0f; c3[1][nt][r] = 0.0f; }
            #pragma unroll
            for (int kt = 0; kt < 8; ++kt) {
                uint af[2][4];
                #pragma unroll
                for (int mm = 0; mm < 2; ++mm) {
                    af[mm][0] = __float_as_uint(c2s[(g + 16*mm)*68     + kt*8 + tg]);
                    af[mm][1] = __float_as_uint(c2s[(g + 8 + 16*mm)*68 + kt*8 + tg]);
                    af[mm][2] = __float_as_uint(c2s[(g + 16*mm)*68     + kt*8 + tg + 4]);
                    af[mm][3] = __float_as_uint(c2s[(g + 8 + 16*mm)*68 + kt*8 + tg + 4]);
                }
                #pragma unroll
                for (int nt2 = 0; nt2 < 8; ++nt2) {
                    float2 bf = w3p[((pp*8+nt2)*8 + g)*36 + kt*4 + tg];
                    mma8(c3[0][nt2], af[0], bf);
                    mma8(c3[1][nt2], af[1], bf);
                }
            }
            // epilogue: max over 16 neighbor rows, +b3, store
            #pragma unroll
            for (int mm = 0; mm < 2; ++mm) {
                #pragma unroll
                for (int nt2 = 0; nt2 < 8; ++nt2) {
                    float v0 = fmaxf(c3[mm][nt2][0], c3[mm][nt2][2]);
                    float v1 = fmaxf(c3[mm][nt2][1], c3[mm][nt2][3]);
                    ull pk = pack2(v0, v1);
                    #pragma unroll
                    for (int st = 4; st < 32; st <<= 1)
                        pk = max2(pk, __shfl_xor_sync(0xffffffffu, pk, st));
                    if (g == nt2) {
                        const int col = (pp*8 + nt2)*8 + 2*tg;
                        float2 b3v = *(float2*)&sb3[col];
                        unpk2(pk, v0, v1);
                        *(float2*)&out[(mm ? rbB : rbA) + col] =
                            make_float2(v0 + b3v.x, v1 + b3v.y);
                    }
                }
            }
        }
        __syncwarp();
    }
}

extern "C" void kernel_launch(void* const* d_in, const int* in_sizes, int n_in,
                              void* d_out, int out_size)
{
    const float* windows = (const float*)d_in[0];
    const float* W1 = (const float*)d_in[1];
    const float* b1 = (const float*)d_in[2];
    const float* W2 = (const float*)d_in[3];
    const float* b2 = (const float*)d_in[4];
    const float* W3 = (const float*)d_in[5];
    const float* b3 = (const float*)d_in[6];
    float* out = (float*)d_out;

    cudaFuncSetAttribute(mini_embedding_mma,
                         cudaFuncAttributeMaxDynamicSharedMemorySize, SMEM_TOTAL);

    const int M = in_sizes[0] / (128 * 3);
    mini_embedding_mma<<<M, NT, SMEM_TOTAL>>>(windows, W1, b1, W2, b2, W3, b3, out);
}

// round 5
// speedup vs baseline: 4.0678x; 1.1914x over previous
#include <cuda_runtime.h>
#include <cstdint>

typedef unsigned long long ull;
typedef unsigned int uint;

#define NT 256

// ---------------- dynamic smem layout (bytes) ----------------
#define OFF_PX   0
#define OFF_PY   512
#define OFF_PZ   1024
#define OFF_SQ   1536
#define OFF_W1   2048     // 3*32*4 = 384
#define OFF_B1   2432     // 128
#define OFF_B2   2560     // 256
#define OFF_B3   2816     // 512
#define OFF_W2L  3328     // float2[8][4][32]  = 8192
#define OFF_W3L  11520    // float2[16][8][32] = 32768
#define OFF_RELX 44288    // 128*16*4 = 8192
#define OFF_RELY 52480
#define OFF_RELZ 60672
#define SMEM_TOTAL 68864

__device__ __forceinline__ uint tf32u(float x) {
    uint r;
    asm("cvt.rna.tf32.f32 %0, %1;" : "=r"(r) : "f"(x));
    return r;
}
__device__ __forceinline__ float tf32f(float x) { return __uint_as_float(tf32u(x)); }

__device__ __forceinline__ void mma8(float c[4], const uint a[4], float2 bf) {
    uint b0 = __float_as_uint(bf.x), b1 = __float_as_uint(bf.y);
    asm volatile(
        "mma.sync.aligned.m16n8k8.row.col.f32.tf32.tf32.f32 "
        "{%0,%1,%2,%3}, {%4,%5,%6,%7}, {%8,%9}, {%0,%1,%2,%3};"
        : "+f"(c[0]), "+f"(c[1]), "+f"(c[2]), "+f"(c[3])
        : "r"(a[0]), "r"(a[1]), "r"(a[2]), "r"(a[3]), "r"(b0), "r"(b1));
}
__device__ __forceinline__ ull pack2(float lo, float hi) {
    ull r;
    asm("mov.b64 %0, {%1, %2};" : "=l"(r) : "f"(lo), "f"(hi));
    return r;
}
__device__ __forceinline__ void unpk2(ull v, float& lo, float& hi) {
    asm("mov.b64 {%0, %1}, %2;" : "=f"(lo), "=f"(hi) : "l"(v));
}
__device__ __forceinline__ ull max2(ull a, ull b) {
    float al, ah, bl, bh;
    unpk2(a, al, ah); unpk2(b, bl, bh);
    return pack2(fmaxf(al, bl), fmaxf(ah, bh));
}

__global__ void __launch_bounds__(NT, 2)
mini_embedding_mma(const float* __restrict__ windows,
                   const float* __restrict__ W1, const float* __restrict__ b1,
                   const float* __restrict__ W2, const float* __restrict__ b2,
                   const float* __restrict__ W3, const float* __restrict__ b3,
                   float* __restrict__ out)
{
    extern __shared__ unsigned char smraw[];
    float* px  = (float*)(smraw + OFF_PX);
    float* py  = (float*)(smraw + OFF_PY);
    float* pz  = (float*)(smraw + OFF_PZ);
    float* sqn = (float*)(smraw + OFF_SQ);
    float* sW1 = (float*)(smraw + OFF_W1);   // [3][32]
    float* sb1 = (float*)(smraw + OFF_B1);
    float* sb2 = (float*)(smraw + OFF_B2);
    float* sb3 = (float*)(smraw + OFF_B3);
    float2* w2L = (float2*)(smraw + OFF_W2L);  // [(nt*4+kt)*32 + lane]
    float2* w3L = (float2*)(smraw + OFF_W3L);  // [(nt2g*8+kt)*32 + lane]
    float* relx = (float*)(smraw + OFF_RELX);
    float* rely = (float*)(smraw + OFF_RELY);
    float* relz = (float*)(smraw + OFF_RELZ);

    const int tid  = threadIdx.x;
    const int w    = tid >> 5;
    const int lane = tid & 31;
    const int g    = lane >> 2;   // row group 0..7
    const int tg   = lane & 3;    // thread-in-group 0..3
    const int m    = blockIdx.x;

    // shuffle-repack source lanes (C-frag -> A-frag permutation)
    const int s1 = (lane & ~3) | (tg >> 1);
    const int s2 = s1 | 2;
    const bool odd = tg & 1;

    // ---- cooperative prep: points + weights (tf32, lane-indexed) ----
    const float* wptr = windows + (size_t)m * 128 * 3;
    for (int i = tid; i < 128; i += NT) {
        float x = wptr[i*3+0], y = wptr[i*3+1], z = wptr[i*3+2];
        px[i] = x; py[i] = y; pz[i] = z;
        sqn[i] = x*x + y*y + z*z;
    }
    for (int i = tid; i < 96;  i += NT) sW1[i] = W1[i];
    for (int i = tid; i < 32;  i += NT) sb1[i] = b1[i];
    for (int i = tid; i < 64;  i += NT) sb2[i] = b2[i];
    for (int i = tid; i < 128; i += NT) sb3[i] = b3[i];
    // w2L[(nt*4+kt)*32 + lane] = (W2[kt*8+tg][nt*8+g], W2[kt*8+tg+4][nt*8+g])
    for (int i = tid; i < 1024; i += NT) {
        int ln = i & 31, kt = (i >> 5) & 3, nt = i >> 7;
        int gg = ln >> 2, tt = ln & 3;
        int n = nt*8 + gg;
        w2L[i] = make_float2(tf32f(W2[(kt*8+tt)*64 + n]),
                             tf32f(W2[(kt*8+tt+4)*64 + n]));
    }
    // w3L[(nt*8+kt)*32 + lane] = (W3[kt*8+tg][nt*8+g], W3[kt*8+tg+4][nt*8+g])
    for (int i = tid; i < 4096; i += NT) {
        int ln = i & 31, kt = (i >> 5) & 7, nt = i >> 8;
        int gg = ln >> 2, tt = ln & 3;
        int n = nt*8 + gg;
        w3L[i] = make_float2(tf32f(W3[(kt*8+tt)*128 + n]),
                             tf32f(W3[(kt*8+tt+4)*128 + n]));
    }
    __syncthreads();

    // ---- warp-local kNN + normalize for this warp's 16 points ----
    const int half = lane >> 4;
    const int n16  = lane & 15;
    #pragma unroll 1
    for (int i4 = 0; i4 < 4; ++i4) {
        #pragma unroll 1
        for (int s = 0; s < 2; ++s) {
            const int q = 16*w + 4*i4 + 2*half + s;
            const float qx = px[q], qy = py[q], qz = pz[q], sq = sqn[q];
            float myv[8];
            const int jb = n16 * 8;
            #pragma unroll
            for (int ii = 0; ii < 8; ++ii) {
                int j = jb + ii;
                float dot = qx*px[j] + qy*py[j] + qz*pz[j];
                myv[ii] = sq + sqn[j] - 2.0f*dot;
            }
            unsigned msk = 0xFFu;
            int myIdx = 0;
            for (int r = 0; r < 16; ++r) {
                float bv = 3.4e38f; int bj = 1 << 30;
                #pragma unroll
                for (int ii = 0; ii < 8; ++ii)
                    if ((msk >> ii) & 1u) { float v = myv[ii]; if (v < bv) { bv = v; bj = jb + ii; } }
                #pragma unroll
                for (int st = 1; st < 16; st <<= 1) {
                    float ov = __shfl_xor_sync(0xffffffffu, bv, st, 16);
                    int   oj = __shfl_xor_sync(0xffffffffu, bj, st, 16);
                    if (ov < bv || (ov == bv && oj < bj)) { bv = ov; bj = oj; }
                }
                if (r == n16) myIdx = bj;
                if (bj >= jb && bj < jb + 8) msk &= ~(1u << (bj - jb));
            }
            float rx = px[myIdx] - qx;
            float ry = py[myIdx] - qy;
            float rz = pz[myIdx] - qz;
            float n2 = rx*rx + ry*ry + rz*rz;
            float mx = n2;
            #pragma unroll
            for (int st = 1; st < 16; st <<= 1)
                mx = fmaxf(mx, __shfl_xor_sync(0xffffffffu, mx, st, 16));
            float invd = 1.0f / fmaxf(sqrtf(mx), 1e-8f);
            relx[q*16 + n16] = rx * invd;
            rely[q*16 + n16] = ry * invd;
            relz[q*16 + n16] = rz * invd;
        }
    }
    __syncwarp();

    // ---- per-chunk GEMM pipeline: 8 chunks of (2 points x 16 neighbors) ----
    #pragma unroll 1
    for (int ch = 0; ch < 8; ++ch) {
        const int pA = 16*w + 2*ch;
        const int pB = pA + 1;

        float rX[4], rY[4], rZ[4];
        rX[0] = relx[pA*16+g];   rY[0] = rely[pA*16+g];   rZ[0] = relz[pA*16+g];
        rX[1] = relx[pA*16+g+8]; rY[1] = rely[pA*16+g+8]; rZ[1] = relz[pA*16+g+8];
        rX[2] = relx[pB*16+g];   rY[2] = rely[pB*16+g];   rZ[2] = relz[pB*16+g];
        rX[3] = relx[pB*16+g+8]; rY[3] = rely[pB*16+g+8]; rZ[3] = relz[pB*16+g+8];

        // h1 in A-fragment layout
        uint afrag[2][4][4];
        #pragma unroll
        for (int j = 0; j < 8; ++j) {
            const int col = tg + 4*j;
            const float w0 = sW1[col], w1 = sW1[32+col], w2 = sW1[64+col], bb = sb1[col];
            const int kt = j >> 1, hi = j & 1;
            #pragma unroll
            for (int mm = 0; mm < 2; ++mm) {
                float hg  = fmaxf(bb + rX[2*mm+0]*w0 + rY[2*mm+0]*w1 + rZ[2*mm+0]*w2, 0.0f);
                float hg8 = fmaxf(bb + rX[2*mm+1]*w0 + rY[2*mm+1]*w1 + rZ[2*mm+1]*w2, 0.0f);
                afrag[mm][kt][hi*2+0] = tf32u(hg);
                afrag[mm][kt][hi*2+1] = tf32u(hg8);
            }
        }

        // layer 2: C2(32x64) = h1 @ W2
        float c2[2][8][4];
        #pragma unroll
        for (int nt = 0; nt < 8; ++nt)
            #pragma unroll
            for (int r = 0; r < 4; ++r) { c2[0][nt][r] = 0.0f; c2[1][nt][r] = 0.0f; }
        #pragma unroll
        for (int kt = 0; kt < 4; ++kt) {
            #pragma unroll
            for (int nt = 0; nt < 8; ++nt) {
                float2 bf = w2L[(nt*4 + kt)*32 + lane];
                mma8(c2[0][nt], afrag[0][kt], bf);
                mma8(c2[1][nt], afrag[1][kt], bf);
            }
        }

        // epilogue 1 + repack: relu(+b2), tf32 round, C-frag -> A-frag via shuffles
        uint af[2][8][4];
        #pragma unroll
        for (int mm = 0; mm < 2; ++mm) {
            #pragma unroll
            for (int nt = 0; nt < 8; ++nt) {
                const int col = nt*8 + 2*tg;
                const float b20 = sb2[col], b21 = sb2[col+1];
                uint r0 = tf32u(fmaxf(c2[mm][nt][0] + b20, 0.0f));
                uint r1 = tf32u(fmaxf(c2[mm][nt][1] + b21, 0.0f));
                uint r2 = tf32u(fmaxf(c2[mm][nt][2] + b20, 0.0f));
                uint r3 = tf32u(fmaxf(c2[mm][nt][3] + b21, 0.0f));
                uint v00 = __shfl_sync(0xffffffffu, r0, s1);
                uint v01 = __shfl_sync(0xffffffffu, r1, s1);
                uint v02 = __shfl_sync(0xffffffffu, r2, s1);
                uint v03 = __shfl_sync(0xffffffffu, r3, s1);
                uint v10 = __shfl_sync(0xffffffffu, r0, s2);
                uint v11 = __shfl_sync(0xffffffffu, r1, s2);
                uint v12 = __shfl_sync(0xffffffffu, r2, s2);
                uint v13 = __shfl_sync(0xffffffffu, r3, s2);
                af[mm][nt][0] = odd ? v01 : v00;
                af[mm][nt][1] = odd ? v03 : v02;
                af[mm][nt][2] = odd ? v11 : v10;
                af[mm][nt][3] = odd ? v13 : v12;
            }
        }

        // layer 3: C3(32x128) = h2 @ W3, 4 passes of (2 pp x 2 nh), c3 tiled
        const size_t rbA = ((size_t)(m*128 + pA)) * 128;
        const size_t rbB = ((size_t)(m*128 + pB)) * 128;
        #pragma unroll 1
        for (int pp = 0; pp < 2; ++pp) {
            #pragma unroll 1
            for (int nh = 0; nh < 2; ++nh) {
                float c3[2][4][4];
                #pragma unroll
                for (int n2 = 0; n2 < 4; ++n2)
                    #pragma unroll
                    for (int r = 0; r < 4; ++r) { c3[0][n2][r] = 0.0f; c3[1][n2][r] = 0.0f; }
                #pragma unroll
                for (int kt = 0; kt < 8; ++kt) {
                    #pragma unroll
                    for (int n2 = 0; n2 < 4; ++n2) {
                        const int ntg = pp*8 + nh*4 + n2;
                        float2 bf = w3L[(ntg*8 + kt)*32 + lane];
                        mma8(c3[0][n2], af[0][kt], bf);
                        mma8(c3[1][n2], af[1][kt], bf);
                    }
                }
                // epilogue: max over 16 neighbor rows, +b3, store
                #pragma unroll
                for (int mm = 0; mm < 2; ++mm) {
                    #pragma unroll
                    for (int n2 = 0; n2 < 4; ++n2) {
                        float v0 = fmaxf(c3[mm][n2][0], c3[mm][n2][2]);
                        float v1 = fmaxf(c3[mm][n2][1], c3[mm][n2][3]);
                        ull pk = pack2(v0, v1);
                        #pragma unroll
                        for (int st = 4; st < 32; st <<= 1)
                            pk = max2(pk, __shfl_xor_sync(0xffffffffu, pk, st));
                        if (g == nh*4 + n2) {
                            const int col = (pp*8 + nh*4 + n2)*8 + 2*tg;
                            float2 b3v = *(float2*)&sb3[col];
                            unpk2(pk, v0, v1);
                            *(float2*)&out[(mm ? rbB : rbA) + col] =
                                make_float2(v0 + b3v.x, v1 + b3v.y);
                        }
                    }
                }
            }
        }
    }
}

extern "C" void kernel_launch(void* const* d_in, const int* in_sizes, int n_in,
                              void* d_out, int out_size)
{
    const float* windows = (const float*)d_in[0];
    const float* W1 = (const float*)d_in[1];
    const float* b1 = (const float*)d_in[2];
    const float* W2 = (const float*)d_in[3];
    const float* b2 = (const float*)d_in[4];
    const float* W3 = (const float*)d_in[5];
    const float* b3 = (const float*)d_in[6];
    float* out = (float*)d_out;

    cudaFuncSetAttribute(mini_embedding_mma,
                         cudaFuncAttributeMaxDynamicSharedMemorySize, SMEM_TOTAL);

    const int M = in_sizes[0] / (128 * 3);
    mini_embedding_mma<<<M, NT, SMEM_TOTAL>>>(windows, W1, b1, W2, b2, W3, b3, out);
}

// round 6
// speedup vs baseline: 4.5724x; 1.1240x over previous
#include <cuda_runtime.h>
#include <cstdint>

typedef unsigned long long ull;
typedef unsigned int uint;

#define NT 256

// ---------------- dynamic smem layout (bytes) ----------------
#define OFF_PX   0
#define OFF_PY   512
#define OFF_PZ   1024
#define OFF_SQ   1536
#define OFF_W1   2048     // 3*32*4 = 384
#define OFF_B1   2432     // 128
#define OFF_B2   2560     // 256
#define OFF_B3   2816     // 512
#define OFF_W2L  3328     // float2[8][4][32]  = 8192
#define OFF_W3L  11520    // float2[16][8][32] = 32768
#define OFF_RELX 44288    // 128*16*4 = 8192
#define OFF_RELY 52480
#define OFF_RELZ 60672
#define SMEM_TOTAL 68864

__device__ __forceinline__ uint tf32u(float x) {
    uint r;
    asm("cvt.rna.tf32.f32 %0, %1;" : "=r"(r) : "f"(x));
    return r;
}
__device__ __forceinline__ float tf32f(float x) { return __uint_as_float(tf32u(x)); }

__device__ __forceinline__ void mma8(float c[4], const uint a[4], float2 bf) {
    uint b0 = __float_as_uint(bf.x), b1 = __float_as_uint(bf.y);
    asm volatile(
        "mma.sync.aligned.m16n8k8.row.col.f32.tf32.tf32.f32 "
        "{%0,%1,%2,%3}, {%4,%5,%6,%7}, {%8,%9}, {%0,%1,%2,%3};"
        : "+f"(c[0]), "+f"(c[1]), "+f"(c[2]), "+f"(c[3])
        : "r"(a[0]), "r"(a[1]), "r"(a[2]), "r"(a[3]), "r"(b0), "r"(b1));
}

// 64-bit shuffle within 16-lane halves
__device__ __forceinline__ ull shflx64(ull v, int st) {
    uint lo = (uint)v, hi = (uint)(v >> 32);
    lo = __shfl_xor_sync(0xffffffffu, lo, st, 16);
    hi = __shfl_xor_sync(0xffffffffu, hi, st, 16);
    return ((ull)hi << 32) | lo;
}

__global__ void __launch_bounds__(NT, 2)
mini_embedding_mma(const float* __restrict__ windows,
                   const float* __restrict__ W1, const float* __restrict__ b1,
                   const float* __restrict__ W2, const float* __restrict__ b2,
                   const float* __restrict__ W3, const float* __restrict__ b3,
                   float* __restrict__ out)
{
    extern __shared__ unsigned char smraw[];
    float* px  = (float*)(smraw + OFF_PX);
    float* py  = (float*)(smraw + OFF_PY);
    float* pz  = (float*)(smraw + OFF_PZ);
    float* sqn = (float*)(smraw + OFF_SQ);
    float* sW1 = (float*)(smraw + OFF_W1);   // [3][32]
    float* sb1 = (float*)(smraw + OFF_B1);
    float* sb2 = (float*)(smraw + OFF_B2);
    float* sb3 = (float*)(smraw + OFF_B3);
    float2* w2L = (float2*)(smraw + OFF_W2L);
    float2* w3L = (float2*)(smraw + OFF_W3L);
    float* relx = (float*)(smraw + OFF_RELX);
    float* rely = (float*)(smraw + OFF_RELY);
    float* relz = (float*)(smraw + OFF_RELZ);

    const int tid  = threadIdx.x;
    const int w    = tid >> 5;
    const int lane = tid & 31;
    const int g    = lane >> 2;   // row group 0..7
    const int tg   = lane & 3;    // thread-in-group 0..3
    const int m    = blockIdx.x;

    const bool g0 = (lane >> 2) & 1;
    const bool g1 = (lane >> 3) & 1;
    const int  g2 = (lane >> 4) & 1;

    // shuffle-repack source lanes (C-frag -> A-frag permutation)
    const int s1 = (lane & ~3) | (tg >> 1);
    const int s2 = s1 | 2;
    const bool odd = tg & 1;

    // ---- cooperative prep ----
    const float* wptr = windows + (size_t)m * 128 * 3;
    for (int i = tid; i < 128; i += NT) {
        float x = wptr[i*3+0], y = wptr[i*3+1], z = wptr[i*3+2];
        px[i] = x; py[i] = y; pz[i] = z;
        sqn[i] = x*x + y*y + z*z;
    }
    for (int i = tid; i < 96;  i += NT) sW1[i] = W1[i];
    for (int i = tid; i < 32;  i += NT) sb1[i] = b1[i];
    for (int i = tid; i < 64;  i += NT) sb2[i] = b2[i];
    for (int i = tid; i < 128; i += NT) sb3[i] = b3[i];
    for (int i = tid; i < 1024; i += NT) {
        int ln = i & 31, kt = (i >> 5) & 3, nt = i >> 7;
        int gg = ln >> 2, tt = ln & 3;
        int n = nt*8 + gg;
        w2L[i] = make_float2(tf32f(W2[(kt*8+tt)*64 + n]),
                             tf32f(W2[(kt*8+tt+4)*64 + n]));
    }
    for (int i = tid; i < 4096; i += NT) {
        int ln = i & 31, kt = (i >> 5) & 7, nt = i >> 8;
        int gg = ln >> 2, tt = ln & 3;
        int n = nt*8 + gg;
        w3L[i] = make_float2(tf32f(W3[(kt*8+tt)*128 + n]),
                             tf32f(W3[(kt*8+tt+4)*128 + n]));
    }
    __syncthreads();

    // ---- warp-local kNN + normalize (u64 lexicographic keys) ----
    const int half = lane >> 4;
    const int n16  = lane & 15;
    #pragma unroll 1
    for (int i4 = 0; i4 < 4; ++i4) {
        #pragma unroll 1
        for (int s = 0; s < 2; ++s) {
            const int q = 16*w + 4*i4 + 2*half + s;
            const float qx = px[q], qy = py[q], qz = pz[q], sq = sqn[q];
            const int jb = n16 * 8;
            ull k[8];
            #pragma unroll
            for (int ii = 0; ii < 8; ++ii) {
                int j = jb + ii;
                float dot = qx*px[j] + qy*py[j] + qz*pz[j];
                float d2 = sq + sqn[j] - 2.0f*dot;
                uint b = __float_as_uint(d2);
                uint key32 = b ^ (uint)((((int)b) >> 31) | 0x80000000);
                k[ii] = ((ull)key32 << 32) | (uint)j;
            }
            int myIdx = 0;
            #pragma unroll 1
            for (int r = 0; r < 16; ++r) {
                ull kmin = k[0];
                #pragma unroll
                for (int ii = 1; ii < 8; ++ii) kmin = (k[ii] < kmin) ? k[ii] : kmin;
                #pragma unroll
                for (int st = 1; st < 16; st <<= 1) {
                    ull o = shflx64(kmin, st);
                    kmin = (o < kmin) ? o : kmin;
                }
                if (r == n16) myIdx = (int)((uint)kmin & 127u);
                #pragma unroll
                for (int ii = 0; ii < 8; ++ii)
                    k[ii] = (k[ii] == kmin) ? ~0ull : k[ii];
            }
            float rx = px[myIdx] - qx;
            float ry = py[myIdx] - qy;
            float rz = pz[myIdx] - qz;
            float n2v = rx*rx + ry*ry + rz*rz;
            float mx = n2v;
            #pragma unroll
            for (int st = 1; st < 16; st <<= 1)
                mx = fmaxf(mx, __shfl_xor_sync(0xffffffffu, mx, st, 16));
            float invd = 1.0f / fmaxf(sqrtf(mx), 1e-8f);
            relx[q*16 + n16] = rx * invd;
            rely[q*16 + n16] = ry * invd;
            relz[q*16 + n16] = rz * invd;
        }
    }
    __syncwarp();

    // ---- per-chunk GEMM pipeline: 8 chunks of (2 points x 16 neighbors) ----
    #pragma unroll 1
    for (int ch = 0; ch < 8; ++ch) {
        const int pA = 16*w + 2*ch;
        const int pB = pA + 1;

        float rX[4], rY[4], rZ[4];
        rX[0] = relx[pA*16+g];   rY[0] = rely[pA*16+g];   rZ[0] = relz[pA*16+g];
        rX[1] = relx[pA*16+g+8]; rY[1] = rely[pA*16+g+8]; rZ[1] = relz[pA*16+g+8];
        rX[2] = relx[pB*16+g];   rY[2] = rely[pB*16+g];   rZ[2] = relz[pB*16+g];
        rX[3] = relx[pB*16+g+8]; rY[3] = rely[pB*16+g+8]; rZ[3] = relz[pB*16+g+8];

        // h1 in A-fragment layout
        uint afrag[2][4][4];
        #pragma unroll
        for (int j = 0; j < 8; ++j) {
            const int col = tg + 4*j;
            const float w0 = sW1[col], w1 = sW1[32+col], w2 = sW1[64+col], bb = sb1[col];
            const int kt = j >> 1, hi = j & 1;
            #pragma unroll
            for (int mm = 0; mm < 2; ++mm) {
                float hg  = fmaxf(bb + rX[2*mm+0]*w0 + rY[2*mm+0]*w1 + rZ[2*mm+0]*w2, 0.0f);
                float hg8 = fmaxf(bb + rX[2*mm+1]*w0 + rY[2*mm+1]*w1 + rZ[2*mm+1]*w2, 0.0f);
                afrag[mm][kt][hi*2+0] = tf32u(hg);
                afrag[mm][kt][hi*2+1] = tf32u(hg8);
            }
        }

        // layer 2
        float c2[2][8][4];
        #pragma unroll
        for (int nt = 0; nt < 8; ++nt)
            #pragma unroll
            for (int r = 0; r < 4; ++r) { c2[0][nt][r] = 0.0f; c2[1][nt][r] = 0.0f; }
        #pragma unroll
        for (int kt = 0; kt < 4; ++kt) {
            #pragma unroll
            for (int nt = 0; nt < 8; ++nt) {
                float2 bf = w2L[(nt*4 + kt)*32 + lane];
                mma8(c2[0][nt], afrag[0][kt], bf);
                mma8(c2[1][nt], afrag[1][kt], bf);
            }
        }

        // epilogue 1 + repack
        uint af[2][8][4];
        #pragma unroll
        for (int mm = 0; mm < 2; ++mm) {
            #pragma unroll
            for (int nt = 0; nt < 8; ++nt) {
                const int col = nt*8 + 2*tg;
                const float b20 = sb2[col], b21 = sb2[col+1];
                uint r0 = tf32u(fmaxf(c2[mm][nt][0] + b20, 0.0f));
                uint r1 = tf32u(fmaxf(c2[mm][nt][1] + b21, 0.0f));
                uint r2 = tf32u(fmaxf(c2[mm][nt][2] + b20, 0.0f));
                uint r3 = tf32u(fmaxf(c2[mm][nt][3] + b21, 0.0f));
                uint v00 = __shfl_sync(0xffffffffu, r0, s1);
                uint v01 = __shfl_sync(0xffffffffu, r1, s1);
                uint v02 = __shfl_sync(0xffffffffu, r2, s1);
                uint v03 = __shfl_sync(0xffffffffu, r3, s1);
                uint v10 = __shfl_sync(0xffffffffu, r0, s2);
                uint v11 = __shfl_sync(0xffffffffu, r1, s2);
                uint v12 = __shfl_sync(0xffffffffu, r2, s2);
                uint v13 = __shfl_sync(0xffffffffu, r3, s2);
                af[mm][nt][0] = odd ? v01 : v00;
                af[mm][nt][1] = odd ? v03 : v02;
                af[mm][nt][2] = odd ? v11 : v10;
                af[mm][nt][3] = odd ? v13 : v12;
            }
        }

        // layer 3 + routed max-reduction epilogue
        const size_t rbA = ((size_t)(m*128 + pA)) * 128;
        const size_t rbB = ((size_t)(m*128 + pB)) * 128;
        #pragma unroll 1
        for (int pp = 0; pp < 2; ++pp) {
            #pragma unroll 1
            for (int nh = 0; nh < 2; ++nh) {
                float c3[2][4][4];
                #pragma unroll
                for (int n2 = 0; n2 < 4; ++n2)
                    #pragma unroll
                    for (int r = 0; r < 4; ++r) { c3[0][n2][r] = 0.0f; c3[1][n2][r] = 0.0f; }
                #pragma unroll
                for (int kt = 0; kt < 8; ++kt) {
                    #pragma unroll
                    for (int n2 = 0; n2 < 4; ++n2) {
                        const int ntg = pp*8 + nh*4 + n2;
                        float2 bf = w3L[(ntg*8 + kt)*32 + lane];
                        mma8(c3[0][n2], af[0][kt], bf);
                        mma8(c3[1][n2], af[1][kt], bf);
                    }
                }
                // routed tree: payload n2 -> lane group with (g&3)==n2
                #pragma unroll
                for (int mm = 0; mm < 2; ++mm) {
                    float P[4][2];
                    #pragma unroll
                    for (int n2 = 0; n2 < 4; ++n2) {
                        P[n2][0] = fmaxf(c3[mm][n2][0], c3[mm][n2][2]);
                        P[n2][1] = fmaxf(c3[mm][n2][1], c3[mm][n2][3]);
                    }
                    // step stride 4 (bit0 of n2)
                    float e0 = g0 ? P[0][0] : P[1][0];
                    float e1 = g0 ? P[0][1] : P[1][1];
                    float e2 = g0 ? P[2][0] : P[3][0];
                    float e3 = g0 ? P[2][1] : P[3][1];
                    float K0v0 = g0 ? P[1][0] : P[0][0];
                    float K0v1 = g0 ? P[1][1] : P[0][1];
                    float K1v0 = g0 ? P[3][0] : P[2][0];
                    float K1v1 = g0 ? P[3][1] : P[2][1];
                    K0v0 = fmaxf(K0v0, __shfl_xor_sync(0xffffffffu, e0, 4));
                    K0v1 = fmaxf(K0v1, __shfl_xor_sync(0xffffffffu, e1, 4));
                    K1v0 = fmaxf(K1v0, __shfl_xor_sync(0xffffffffu, e2, 4));
                    K1v1 = fmaxf(K1v1, __shfl_xor_sync(0xffffffffu, e3, 4));
                    // step stride 8 (bit1 of n2)
                    float f0  = g1 ? K0v0 : K1v0;
                    float f1  = g1 ? K0v1 : K1v1;
                    float Rv0 = g1 ? K1v0 : K0v0;
                    float Rv1 = g1 ? K1v1 : K0v1;
                    Rv0 = fmaxf(Rv0, __shfl_xor_sync(0xffffffffu, f0, 8));
                    Rv1 = fmaxf(Rv1, __shfl_xor_sync(0xffffffffu, f1, 8));
                    // step stride 16 (reduce remaining dim)
                    Rv0 = fmaxf(Rv0, __shfl_xor_sync(0xffffffffu, Rv0, 16));
                    Rv1 = fmaxf(Rv1, __shfl_xor_sync(0xffffffffu, Rv1, 16));
                    // lane holds final payload for n2 = g&3; half the lanes write
                    if (g2 == nh) {
                        const int col = (pp*8 + nh*4 + (g & 3))*8 + 2*tg;
                        float2 b3v = *(float2*)&sb3[col];
                        *(float2*)&out[(mm ? rbB : rbA) + col] =
                            make_float2(Rv0 + b3v.x, Rv1 + b3v.y);
                    }
                }
            }
        }
    }
}

extern "C" void kernel_launch(void* const* d_in, const int* in_sizes, int n_in,
                              void* d_out, int out_size)
{
    const float* windows = (const float*)d_in[0];
    const float* W1 = (const float*)d_in[1];
    const float* b1 = (const float*)d_in[2];
    const float* W2 = (const float*)d_in[3];
    const float* b2 = (const float*)d_in[4];
    const float* W3 = (const float*)d_in[5];
    const float* b3 = (const float*)d_in[6];
    float* out = (float*)d_out;

    cudaFuncSetAttribute(mini_embedding_mma,
                         cudaFuncAttributeMaxDynamicSharedMemorySize, SMEM_TOTAL);

    const int M = in_sizes[0] / (128 * 3);
    mini_embedding_mma<<<M, NT, SMEM_TOTAL>>>(windows, W1, b1, W2, b2, W3, b3, out);
}

// round 7
// speedup vs baseline: 6.1352x; 1.3418x over previous
#include <cuda_runtime.h>
#include <cstdint>

typedef unsigned long long ull;
typedef unsigned int uint;

#define NT 256

// ---------------- dynamic smem layout (bytes) ----------------
#define OFF_PX   0
#define OFF_PY   512
#define OFF_PZ   1024
#define OFF_SQ   1536
#define OFF_W1   2048     // 3*32*4 = 384
#define OFF_B1   2432     // 128
#define OFF_B2   2560     // 256
#define OFF_B3   2816     // 512
#define OFF_W2L  3328     // float2[8][4][32]  = 8192
#define OFF_W3L  11520    // float2[16][8][32] = 32768
#define OFF_RELX 44288    // 128*16*4 = 8192
#define OFF_RELY 52480
#define OFF_RELZ 60672
#define SMEM_TOTAL 68864

__device__ __forceinline__ uint tf32u(float x) {
    uint r;
    asm("cvt.rna.tf32.f32 %0, %1;" : "=r"(r) : "f"(x));
    return r;
}
__device__ __forceinline__ float tf32f(float x) { return __uint_as_float(tf32u(x)); }

__device__ __forceinline__ void mma8(float c[4], const uint a[4], float2 bf) {
    uint b0 = __float_as_uint(bf.x), b1 = __float_as_uint(bf.y);
    asm volatile(
        "mma.sync.aligned.m16n8k8.row.col.f32.tf32.tf32.f32 "
        "{%0,%1,%2,%3}, {%4,%5,%6,%7}, {%8,%9}, {%0,%1,%2,%3};"
        : "+f"(c[0]), "+f"(c[1]), "+f"(c[2]), "+f"(c[3])
        : "r"(a[0]), "r"(a[1]), "r"(a[2]), "r"(a[3]), "r"(b0), "r"(b1));
}

// float bits -> order-preserving u32
__device__ __forceinline__ uint fmono(float x) {
    uint b = __float_as_uint(x);
    return b ^ (uint)((((int)b) >> 31) | 0x80000000);
}
__device__ __forceinline__ void cas(uint& a, uint& b) {
    uint lo = umin(a, b), hi = umax(a, b);
    a = lo; b = hi;
}
// Batcher 19-comparator sorting network for 8 elements
__device__ __forceinline__ void sort8(uint k[8]) {
    cas(k[0],k[1]); cas(k[2],k[3]); cas(k[4],k[5]); cas(k[6],k[7]);
    cas(k[0],k[2]); cas(k[1],k[3]); cas(k[4],k[6]); cas(k[5],k[7]);
    cas(k[1],k[2]); cas(k[5],k[6]); cas(k[0],k[4]); cas(k[1],k[5]);
    cas(k[2],k[6]); cas(k[3],k[7]);
    cas(k[1],k[4]); cas(k[3],k[6]);
    cas(k[2],k[4]); cas(k[3],k[5]);
    cas(k[3],k[4]);
}
__device__ __forceinline__ void pop_shift(uint k[8], uint kmin) {
    if (k[0] == kmin) {
        k[0]=k[1]; k[1]=k[2]; k[2]=k[3]; k[3]=k[4];
        k[4]=k[5]; k[5]=k[6]; k[6]=k[7]; k[7]=0xFFFFFFFFu;
    }
}

__global__ void __launch_bounds__(NT, 2)
mini_embedding_mma(const float* __restrict__ windows,
                   const float* __restrict__ W1, const float* __restrict__ b1,
                   const float* __restrict__ W2, const float* __restrict__ b2,
                   const float* __restrict__ W3, const float* __restrict__ b3,
                   float* __restrict__ out)
{
    extern __shared__ unsigned char smraw[];
    float* px  = (float*)(smraw + OFF_PX);
    float* py  = (float*)(smraw + OFF_PY);
    float* pz  = (float*)(smraw + OFF_PZ);
    float* sqn = (float*)(smraw + OFF_SQ);
    float* sW1 = (float*)(smraw + OFF_W1);
    float* sb1 = (float*)(smraw + OFF_B1);
    float* sb2 = (float*)(smraw + OFF_B2);
    float* sb3 = (float*)(smraw + OFF_B3);
    float2* w2L = (float2*)(smraw + OFF_W2L);
    float2* w3L = (float2*)(smraw + OFF_W3L);
    float* relx = (float*)(smraw + OFF_RELX);
    float* rely = (float*)(smraw + OFF_RELY);
    float* relz = (float*)(smraw + OFF_RELZ);

    const int tid  = threadIdx.x;
    const int w    = tid >> 5;
    const int lane = tid & 31;
    const int g    = lane >> 2;
    const int tg   = lane & 3;
    const int m    = blockIdx.x;

    const bool g0 = (lane >> 2) & 1;
    const bool g1 = (lane >> 3) & 1;
    const int  g2 = (lane >> 4) & 1;

    const int s1 = (lane & ~3) | (tg >> 1);
    const int s2 = s1 | 2;
    const bool odd = tg & 1;

    // ---- cooperative prep ----
    const float* wptr = windows + (size_t)m * 128 * 3;
    for (int i = tid; i < 128; i += NT) {
        float x = wptr[i*3+0], y = wptr[i*3+1], z = wptr[i*3+2];
        px[i] = x; py[i] = y; pz[i] = z;
        sqn[i] = x*x + y*y + z*z;
    }
    for (int i = tid; i < 96;  i += NT) sW1[i] = W1[i];
    for (int i = tid; i < 32;  i += NT) sb1[i] = b1[i];
    for (int i = tid; i < 64;  i += NT) sb2[i] = b2[i];
    for (int i = tid; i < 128; i += NT) sb3[i] = b3[i];
    for (int i = tid; i < 1024; i += NT) {
        int ln = i & 31, kt = (i >> 5) & 3, nt = i >> 7;
        int gg = ln >> 2, tt = ln & 3;
        int n = nt*8 + gg;
        w2L[i] = make_float2(tf32f(W2[(kt*8+tt)*64 + n]),
                             tf32f(W2[(kt*8+tt+4)*64 + n]));
    }
    for (int i = tid; i < 4096; i += NT) {
        int ln = i & 31, kt = (i >> 5) & 7, nt = i >> 8;
        int gg = ln >> 2, tt = ln & 3;
        int n = nt*8 + gg;
        w3L[i] = make_float2(tf32f(W3[(kt*8+tt)*128 + n]),
                             tf32f(W3[(kt*8+tt+4)*128 + n]));
    }
    __syncthreads();

    // ---- warp-local kNN + normalize: 32-bit keys, sorted lists, 2-query ILP ----
    const int half = lane >> 4;
    const int n16  = lane & 15;
    const int jb   = n16 * 8;
    #pragma unroll 1
    for (int i4 = 0; i4 < 4; ++i4) {
        const int q0 = 16*w + 4*i4 + 2*half;
        const int q1 = q0 + 1;
        const float qx0 = px[q0], qy0 = py[q0], qz0 = pz[q0], sq0 = sqn[q0];
        const float qx1 = px[q1], qy1 = py[q1], qz1 = pz[q1], sq1 = sqn[q1];
        uint k0[8], k1[8];
        #pragma unroll
        for (int ii = 0; ii < 8; ++ii) {
            const int j = jb + ii;
            const float xj = px[j], yj = py[j], zj = pz[j], sj = sqn[j];
            float d0 = sq0 + sj - 2.0f*(qx0*xj + qy0*yj + qz0*zj);
            float d1 = sq1 + sj - 2.0f*(qx1*xj + qy1*yj + qz1*zj);
            k0[ii] = (fmono(d0) & 0xFFFFFF80u) | (uint)j;
            k1[ii] = (fmono(d1) & 0xFFFFFF80u) | (uint)j;
        }
        sort8(k0); sort8(k1);
        int idx0 = 0, idx1 = 0;
        #pragma unroll
        for (int r = 0; r < 16; ++r) {
            uint m0 = k0[0], m1 = k1[0];
            #pragma unroll
            for (int st = 1; st < 16; st <<= 1) {
                m0 = umin(m0, __shfl_xor_sync(0xffffffffu, m0, st, 16));
                m1 = umin(m1, __shfl_xor_sync(0xffffffffu, m1, st, 16));
            }
            if (r == n16) { idx0 = (int)(m0 & 127u); idx1 = (int)(m1 & 127u); }
            pop_shift(k0, m0);
            pop_shift(k1, m1);
        }
        float rx0 = px[idx0] - qx0, ry0 = py[idx0] - qy0, rz0 = pz[idx0] - qz0;
        float rx1 = px[idx1] - qx1, ry1 = py[idx1] - qy1, rz1 = pz[idx1] - qz1;
        float mx0 = rx0*rx0 + ry0*ry0 + rz0*rz0;
        float mx1 = rx1*rx1 + ry1*ry1 + rz1*rz1;
        #pragma unroll
        for (int st = 1; st < 16; st <<= 1) {
            mx0 = fmaxf(mx0, __shfl_xor_sync(0xffffffffu, mx0, st, 16));
            mx1 = fmaxf(mx1, __shfl_xor_sync(0xffffffffu, mx1, st, 16));
        }
        float inv0 = 1.0f / fmaxf(sqrtf(mx0), 1e-8f);
        float inv1 = 1.0f / fmaxf(sqrtf(mx1), 1e-8f);
        relx[q0*16 + n16] = rx0 * inv0;
        rely[q0*16 + n16] = ry0 * inv0;
        relz[q0*16 + n16] = rz0 * inv0;
        relx[q1*16 + n16] = rx1 * inv1;
        rely[q1*16 + n16] = ry1 * inv1;
        relz[q1*16 + n16] = rz1 * inv1;
    }
    __syncwarp();

    // ---- per-chunk GEMM pipeline: 8 chunks of (2 points x 16 neighbors) ----
    #pragma unroll 1
    for (int ch = 0; ch < 8; ++ch) {
        const int pA = 16*w + 2*ch;
        const int pB = pA + 1;

        float rX[4], rY[4], rZ[4];
        rX[0] = relx[pA*16+g];   rY[0] = rely[pA*16+g];   rZ[0] = relz[pA*16+g];
        rX[1] = relx[pA*16+g+8]; rY[1] = rely[pA*16+g+8]; rZ[1] = relz[pA*16+g+8];
        rX[2] = relx[pB*16+g];   rY[2] = rely[pB*16+g];   rZ[2] = relz[pB*16+g];
        rX[3] = relx[pB*16+g+8]; rY[3] = rely[pB*16+g+8]; rZ[3] = relz[pB*16+g+8];

        uint afrag[2][4][4];
        #pragma unroll
        for (int j = 0; j < 8; ++j) {
            const int col = tg + 4*j;
            const float w0 = sW1[col], w1 = sW1[32+col], w2 = sW1[64+col], bb = sb1[col];
            const int kt = j >> 1, hi = j & 1;
            #pragma unroll
            for (int mm = 0; mm < 2; ++mm) {
                float hg  = fmaxf(bb + rX[2*mm+0]*w0 + rY[2*mm+0]*w1 + rZ[2*mm+0]*w2, 0.0f);
                float hg8 = fmaxf(bb + rX[2*mm+1]*w0 + rY[2*mm+1]*w1 + rZ[2*mm+1]*w2, 0.0f);
                afrag[mm][kt][hi*2+0] = tf32u(hg);
                afrag[mm][kt][hi*2+1] = tf32u(hg8);
            }
        }

        // layer 2
        float c2[2][8][4];
        #pragma unroll
        for (int nt = 0; nt < 8; ++nt)
            #pragma unroll
            for (int r = 0; r < 4; ++r) { c2[0][nt][r] = 0.0f; c2[1][nt][r] = 0.0f; }
        #pragma unroll
        for (int kt = 0; kt < 4; ++kt) {
            #pragma unroll
            for (int nt = 0; nt < 8; ++nt) {
                float2 bf = w2L[(nt*4 + kt)*32 + lane];
                mma8(c2[0][nt], afrag[0][kt], bf);
                mma8(c2[1][nt], afrag[1][kt], bf);
            }
        }

        // epilogue 1 + repack
        uint af[2][8][4];
        #pragma unroll
        for (int mm = 0; mm < 2; ++mm) {
            #pragma unroll
            for (int nt = 0; nt < 8; ++nt) {
                const int col = nt*8 + 2*tg;
                const float b20 = sb2[col], b21 = sb2[col+1];
                uint r0 = tf32u(fmaxf(c2[mm][nt][0] + b20, 0.0f));
                uint r1 = tf32u(fmaxf(c2[mm][nt][1] + b21, 0.0f));
                uint r2 = tf32u(fmaxf(c2[mm][nt][2] + b20, 0.0f));
                uint r3 = tf32u(fmaxf(c2[mm][nt][3] + b21, 0.0f));
                uint v00 = __shfl_sync(0xffffffffu, r0, s1);
                uint v01 = __shfl_sync(0xffffffffu, r1, s1);
                uint v02 = __shfl_sync(0xffffffffu, r2, s1);
                uint v03 = __shfl_sync(0xffffffffu, r3, s1);
                uint v10 = __shfl_sync(0xffffffffu, r0, s2);
                uint v11 = __shfl_sync(0xffffffffu, r1, s2);
                uint v12 = __shfl_sync(0xffffffffu, r2, s2);
                uint v13 = __shfl_sync(0xffffffffu, r3, s2);
                af[mm][nt][0] = odd ? v01 : v00;
                af[mm][nt][1] = odd ? v03 : v02;
                af[mm][nt][2] = odd ? v11 : v10;
                af[mm][nt][3] = odd ? v13 : v12;
            }
        }

        // layer 3 + routed max-reduction epilogue
        const size_t rbA = ((size_t)(m*128 + pA)) * 128;
        const size_t rbB = ((size_t)(m*128 + pB)) * 128;
        #pragma unroll 1
        for (int pp = 0; pp < 2; ++pp) {
            #pragma unroll 1
            for (int nh = 0; nh < 2; ++nh) {
                float c3[2][4][4];
                #pragma unroll
                for (int n2 = 0; n2 < 4; ++n2)
                    #pragma unroll
                    for (int r = 0; r < 4; ++r) { c3[0][n2][r] = 0.0f; c3[1][n2][r] = 0.0f; }
                #pragma unroll
                for (int kt = 0; kt < 8; ++kt) {
                    #pragma unroll
                    for (int n2 = 0; n2 < 4; ++n2) {
                        const int ntg = pp*8 + nh*4 + n2;
                        float2 bf = w3L[(ntg*8 + kt)*32 + lane];
                        mma8(c3[0][n2], af[0][kt], bf);
                        mma8(c3[1][n2], af[1][kt], bf);
                    }
                }
                #pragma unroll
                for (int mm = 0; mm < 2; ++mm) {
                    float P[4][2];
                    #pragma unroll
                    for (int n2 = 0; n2 < 4; ++n2) {
                        P[n2][0] = fmaxf(c3[mm][n2][0], c3[mm][n2][2]);
                        P[n2][1] = fmaxf(c3[mm][n2][1], c3[mm][n2][3]);
                    }
                    float e0 = g0 ? P[0][0] : P[1][0];
                    float e1 = g0 ? P[0][1] : P[1][1];
                    float e2 = g0 ? P[2][0] : P[3][0];
                    float e3 = g0 ? P[2][1] : P[3][1];
                    float K0v0 = g0 ? P[1][0] : P[0][0];
                    float K0v1 = g0 ? P[1][1] : P[0][1];
                    float K1v0 = g0 ? P[3][0] : P[2][0];
                    float K1v1 = g0 ? P[3][1] : P[2][1];
                    K0v0 = fmaxf(K0v0, __shfl_xor_sync(0xffffffffu, e0, 4));
                    K0v1 = fmaxf(K0v1, __shfl_xor_sync(0xffffffffu, e1, 4));
                    K1v0 = fmaxf(K1v0, __shfl_xor_sync(0xffffffffu, e2, 4));
                    K1v1 = fmaxf(K1v1, __shfl_xor_sync(0xffffffffu, e3, 4));
                    float f0  = g1 ? K0v0 : K1v0;
                    float f1  = g1 ? K0v1 : K1v1;
                    float Rv0 = g1 ? K1v0 : K0v0;
                    float Rv1 = g1 ? K1v1 : K0v1;
                    Rv0 = fmaxf(Rv0, __shfl_xor_sync(0xffffffffu, f0, 8));
                    Rv1 = fmaxf(Rv1, __shfl_xor_sync(0xffffffffu, f1, 8));
                    Rv0 = fmaxf(Rv0, __shfl_xor_sync(0xffffffffu, Rv0, 16));
                    Rv1 = fmaxf(Rv1, __shfl_xor_sync(0xffffffffu, Rv1, 16));
                    if (g2 == nh) {
                        const int col = (pp*8 + nh*4 + (g & 3))*8 + 2*tg;
                        float2 b3v = *(float2*)&sb3[col];
                        *(float2*)&out[(mm ? rbB : rbA) + col] =
                            make_float2(Rv0 + b3v.x, Rv1 + b3v.y);
                    }
                }
            }
        }
    }
}

extern "C" void kernel_launch(void* const* d_in, const int* in_sizes, int n_in,
                              void* d_out, int out_size)
{
    const float* windows = (const float*)d_in[0];
    const float* W1 = (const float*)d_in[1];
    const float* b1 = (const float*)d_in[2];
    const float* W2 = (const float*)d_in[3];
    const float* b2 = (const float*)d_in[4];
    const float* W3 = (const float*)d_in[5];
    const float* b3 = (const float*)d_in[6];
    float* out = (float*)d_out;

    cudaFuncSetAttribute(mini_embedding_mma,
                         cudaFuncAttributeMaxDynamicSharedMemorySize, SMEM_TOTAL);

    const int M = in_sizes[0] / (128 * 3);
    mini_embedding_mma<<<M, NT, SMEM_TOTAL>>>(windows, W1, b1, W2, b2, W3, b3, out);
}

// round 9
// speedup vs baseline: 6.6938x; 1.0911x over previous
#include <cuda_runtime.h>
#include <cstdint>

typedef unsigned long long ull;
typedef unsigned int uint;

#define NT 256

// ---------------- dynamic smem layout (bytes) ----------------
#define OFF_PX   0
#define OFF_PY   512
#define OFF_PZ   1024
#define OFF_SQ   1536
#define OFF_W1   2048     // 3*32*4 = 384
#define OFF_B1   2432     // 128
#define OFF_B2   2560     // 256
#define OFF_B3   2816     // 512
#define OFF_W2L  3328     // float2[8][4][32]  = 8192
#define OFF_W3L  11520    // float2[16][8][32] = 32768
#define OFF_RELX 44288    // 128*16*4 = 8192
#define OFF_RELY 52480
#define OFF_RELZ 60672
#define SMEM_TOTAL 68864

__device__ __forceinline__ uint tf32u(float x) {
    uint r;
    asm("cvt.rna.tf32.f32 %0, %1;" : "=r"(r) : "f"(x));
    return r;
}
__device__ __forceinline__ float tf32f(float x) { return __uint_as_float(tf32u(x)); }

__device__ __forceinline__ void mma8(float c[4], const uint a[4], float2 bf) {
    uint b0 = __float_as_uint(bf.x), b1 = __float_as_uint(bf.y);
    asm volatile(
        "mma.sync.aligned.m16n8k8.row.col.f32.tf32.tf32.f32 "
        "{%0,%1,%2,%3}, {%4,%5,%6,%7}, {%8,%9}, {%0,%1,%2,%3};"
        : "+f"(c[0]), "+f"(c[1]), "+f"(c[2]), "+f"(c[3])
        : "r"(a[0]), "r"(a[1]), "r"(a[2]), "r"(a[3]), "r"(b0), "r"(b1));
}

// hidden-basis permutation within each 8-column block:
// original col at stored position q:  pinv(q) = (q&1) ? (q>>1)+4 : (q>>1)
// With w2L output columns stored in this permuted order, the layer-2 C-frag
// rename {c0,c2,c1,c3} puts ORIGINAL h2 column p at A-frag k-position p,
// so w3L is loaded with UNPERMUTED rows.
__device__ __host__ __forceinline__ int pinv(int q) {
    return (q & 1) ? ((q >> 1) + 4) : (q >> 1);
}

// float bits -> order-preserving u32
__device__ __forceinline__ uint fmono(float x) {
    uint b = __float_as_uint(x);
    return b ^ (uint)((((int)b) >> 31) | 0x80000000);
}
__device__ __forceinline__ void cas(uint& a, uint& b) {
    uint lo = umin(a, b), hi = umax(a, b);
    a = lo; b = hi;
}
__device__ __forceinline__ void sort8(uint k[8]) {
    cas(k[0],k[1]); cas(k[2],k[3]); cas(k[4],k[5]); cas(k[6],k[7]);
    cas(k[0],k[2]); cas(k[1],k[3]); cas(k[4],k[6]); cas(k[5],k[7]);
    cas(k[1],k[2]); cas(k[5],k[6]); cas(k[0],k[4]); cas(k[1],k[5]);
    cas(k[2],k[6]); cas(k[3],k[7]);
    cas(k[1],k[4]); cas(k[3],k[6]);
    cas(k[2],k[4]); cas(k[3],k[5]);
    cas(k[3],k[4]);
}
__device__ __forceinline__ void pop_shift(uint k[8], uint kmin) {
    if (k[0] == kmin) {
        k[0]=k[1]; k[1]=k[2]; k[2]=k[3]; k[3]=k[4];
        k[4]=k[5]; k[5]=k[6]; k[6]=k[7]; k[7]=0xFFFFFFFFu;
    }
}

__global__ void __launch_bounds__(NT, 2)
mini_embedding_mma(const float* __restrict__ windows,
                   const float* __restrict__ W1, const float* __restrict__ b1,
                   const float* __restrict__ W2, const float* __restrict__ b2,
                   const float* __restrict__ W3, const float* __restrict__ b3,
                   float* __restrict__ out)
{
    extern __shared__ unsigned char smraw[];
    float* px  = (float*)(smraw + OFF_PX);
    float* py  = (float*)(smraw + OFF_PY);
    float* pz  = (float*)(smraw + OFF_PZ);
    float* sqn = (float*)(smraw + OFF_SQ);
    float* sW1 = (float*)(smraw + OFF_W1);
    float* sb1 = (float*)(smraw + OFF_B1);
    float* sb2 = (float*)(smraw + OFF_B2);   // permuted by pi
    float* sb3 = (float*)(smraw + OFF_B3);
    float2* w2L = (float2*)(smraw + OFF_W2L);  // output cols permuted by pi
    float2* w3L = (float2*)(smraw + OFF_W3L);  // UNPERMUTED
    float* relx = (float*)(smraw + OFF_RELX);
    float* rely = (float*)(smraw + OFF_RELY);
    float* relz = (float*)(smraw + OFF_RELZ);

    const int tid  = threadIdx.x;
    const int w    = tid >> 5;
    const int lane = tid & 31;
    const int g    = lane >> 2;
    const int tg   = lane & 3;
    const int m    = blockIdx.x;

    const bool g0 = (lane >> 2) & 1;
    const bool g1 = (lane >> 3) & 1;
    const int  g2 = (lane >> 4) & 1;

    // ---- cooperative prep ----
    const float* wptr = windows + (size_t)m * 128 * 3;
    for (int i = tid; i < 128; i += NT) {
        float x = wptr[i*3+0], y = wptr[i*3+1], z = wptr[i*3+2];
        px[i] = x; py[i] = y; pz[i] = z;
        sqn[i] = x*x + y*y + z*z;
    }
    for (int i = tid; i < 96;  i += NT) sW1[i] = W1[i];
    for (int i = tid; i < 32;  i += NT) sb1[i] = b1[i];
    // b2 permuted: stored position q holds b2[pinv(q)]
    for (int i = tid; i < 64;  i += NT) sb2[i] = b2[(i & ~7) | pinv(i & 7)];
    for (int i = tid; i < 128; i += NT) sb3[i] = b3[i];
    // w2L: B-frag for layer2; output col position gg holds original col pinv(gg)
    for (int i = tid; i < 1024; i += NT) {
        int ln = i & 31, kt = (i >> 5) & 3, nt = i >> 7;
        int gg = ln >> 2, tt = ln & 3;
        int c = nt*8 + pinv(gg);
        w2L[i] = make_float2(tf32f(W2[(kt*8+tt)*64 + c]),
                             tf32f(W2[(kt*8+tt+4)*64 + c]));
    }
    // w3L: B-frag for layer3; rows UNPERMUTED (A-frag already in original basis)
    for (int i = tid; i < 4096; i += NT) {
        int ln = i & 31, kt = (i >> 5) & 7, ntg = i >> 8;
        int gg = ln >> 2, tt = ln & 3;
        int n = ntg*8 + gg;
        w3L[i] = make_float2(tf32f(W3[(kt*8+tt)*128 + n]),
                             tf32f(W3[(kt*8+tt+4)*128 + n]));
    }
    __syncthreads();

    // ---- warp-local kNN + normalize: 32-bit keys, sorted lists, 2-query ILP ----
    const int half = lane >> 4;
    const int n16  = lane & 15;
    const int jb   = n16 * 8;
    #pragma unroll 1
    for (int i4 = 0; i4 < 4; ++i4) {
        const int q0 = 16*w + 4*i4 + 2*half;
        const int q1 = q0 + 1;
        const float qx0 = px[q0], qy0 = py[q0], qz0 = pz[q0], sq0 = sqn[q0];
        const float qx1 = px[q1], qy1 = py[q1], qz1 = pz[q1], sq1 = sqn[q1];
        uint k0[8], k1[8];
        #pragma unroll
        for (int ii = 0; ii < 8; ++ii) {
            const int j = jb + ii;
            const float xj = px[j], yj = py[j], zj = pz[j], sj = sqn[j];
            float d0 = sq0 + sj - 2.0f*(qx0*xj + qy0*yj + qz0*zj);
            float d1 = sq1 + sj - 2.0f*(qx1*xj + qy1*yj + qz1*zj);
            k0[ii] = (fmono(d0) & 0xFFFFFF80u) | (uint)j;
            k1[ii] = (fmono(d1) & 0xFFFFFF80u) | (uint)j;
        }
        sort8(k0); sort8(k1);
        int idx0 = 0, idx1 = 0;
        #pragma unroll
        for (int r = 0; r < 16; ++r) {
            uint m0 = k0[0], m1 = k1[0];
            #pragma unroll
            for (int st = 1; st < 16; st <<= 1) {
                m0 = umin(m0, __shfl_xor_sync(0xffffffffu, m0, st, 16));
                m1 = umin(m1, __shfl_xor_sync(0xffffffffu, m1, st, 16));
            }
            if (r == n16) { idx0 = (int)(m0 & 127u); idx1 = (int)(m1 & 127u); }
            pop_shift(k0, m0);
            pop_shift(k1, m1);
        }
        float rx0 = px[idx0] - qx0, ry0 = py[idx0] - qy0, rz0 = pz[idx0] - qz0;
        float rx1 = px[idx1] - qx1, ry1 = py[idx1] - qy1, rz1 = pz[idx1] - qz1;
        float mx0 = rx0*rx0 + ry0*ry0 + rz0*rz0;
        float mx1 = rx1*rx1 + ry1*ry1 + rz1*rz1;
        #pragma unroll
        for (int st = 1; st < 16; st <<= 1) {
            mx0 = fmaxf(mx0, __shfl_xor_sync(0xffffffffu, mx0, st, 16));
            mx1 = fmaxf(mx1, __shfl_xor_sync(0xffffffffu, mx1, st, 16));
        }
        float inv0 = 1.0f / fmaxf(sqrtf(mx0), 1e-8f);
        float inv1 = 1.0f / fmaxf(sqrtf(mx1), 1e-8f);
        relx[q0*16 + n16] = rx0 * inv0;
        rely[q0*16 + n16] = ry0 * inv0;
        relz[q0*16 + n16] = rz0 * inv0;
        relx[q1*16 + n16] = rx1 * inv1;
        rely[q1*16 + n16] = ry1 * inv1;
        relz[q1*16 + n16] = rz1 * inv1;
    }
    __syncwarp();

    // ---- per-chunk GEMM pipeline: 8 chunks of (2 points x 16 neighbors) ----
    #pragma unroll 1
    for (int ch = 0; ch < 8; ++ch) {
        const int pA = 16*w + 2*ch;
        const int pB = pA + 1;

        float rX[4], rY[4], rZ[4];
        rX[0] = relx[pA*16+g];   rY[0] = rely[pA*16+g];   rZ[0] = relz[pA*16+g];
        rX[1] = relx[pA*16+g+8]; rY[1] = rely[pA*16+g+8]; rZ[1] = relz[pA*16+g+8];
        rX[2] = relx[pB*16+g];   rY[2] = rely[pB*16+g];   rZ[2] = relz[pB*16+g];
        rX[3] = relx[pB*16+g+8]; rY[3] = rely[pB*16+g+8]; rZ[3] = relz[pB*16+g+8];

        uint afrag[2][4][4];
        #pragma unroll
        for (int j = 0; j < 8; ++j) {
            const int col = tg + 4*j;
            const float w0 = sW1[col], w1 = sW1[32+col], w2 = sW1[64+col], bb = sb1[col];
            const int kt = j >> 1, hi = j & 1;
            #pragma unroll
            for (int mm = 0; mm < 2; ++mm) {
                float hg  = fmaxf(bb + rX[2*mm+0]*w0 + rY[2*mm+0]*w1 + rZ[2*mm+0]*w2, 0.0f);
                float hg8 = fmaxf(bb + rX[2*mm+1]*w0 + rY[2*mm+1]*w1 + rZ[2*mm+1]*w2, 0.0f);
                afrag[mm][kt][hi*2+0] = tf32u(hg);
                afrag[mm][kt][hi*2+1] = tf32u(hg8);
            }
        }

        // layer 2 (output columns in permuted basis)
        float c2[2][8][4];
        #pragma unroll
        for (int nt = 0; nt < 8; ++nt)
            #pragma unroll
            for (int r = 0; r < 4; ++r) { c2[0][nt][r] = 0.0f; c2[1][nt][r] = 0.0f; }
        #pragma unroll
        for (int kt = 0; kt < 4; ++kt) {
            #pragma unroll
            for (int nt = 0; nt < 8; ++nt) {
                float2 bf = w2L[(nt*4 + kt)*32 + lane];
                mma8(c2[0][nt], afrag[0][kt], bf);
                mma8(c2[1][nt], afrag[1][kt], bf);
            }
        }

        // epilogue 1: relu(+b2), tf32 round; C-frag IS the A-frag (register rename)
        // stored col 2tg   -> original col tg   -> A-frag k-position tg    (slots 0,1)
        // stored col 2tg+1 -> original col tg+4 -> A-frag k-position tg+4  (slots 2,3)
        uint af[2][8][4];
        #pragma unroll
        for (int mm = 0; mm < 2; ++mm) {
            #pragma unroll
            for (int nt = 0; nt < 8; ++nt) {
                const int col = nt*8 + 2*tg;
                const float b20 = sb2[col], b21 = sb2[col+1];
                af[mm][nt][0] = tf32u(fmaxf(c2[mm][nt][0] + b20, 0.0f));
                af[mm][nt][1] = tf32u(fmaxf(c2[mm][nt][2] + b20, 0.0f));
                af[mm][nt][2] = tf32u(fmaxf(c2[mm][nt][1] + b21, 0.0f));
                af[mm][nt][3] = tf32u(fmaxf(c2[mm][nt][3] + b21, 0.0f));
            }
        }

        // layer 3 + routed max-reduction epilogue
        const size_t rbA = ((size_t)(m*128 + pA)) * 128;
        const size_t rbB = ((size_t)(m*128 + pB)) * 128;
        #pragma unroll 1
        for (int pp = 0; pp < 2; ++pp) {
            #pragma unroll 1
            for (int nh = 0; nh < 2; ++nh) {
                float c3[2][4][4];
                #pragma unroll
                for (int n2 = 0; n2 < 4; ++n2)
                    #pragma unroll
                    for (int r = 0; r < 4; ++r) { c3[0][n2][r] = 0.0f; c3[1][n2][r] = 0.0f; }
                #pragma unroll
                for (int kt = 0; kt < 8; ++kt) {
                    #pragma unroll
                    for (int n2 = 0; n2 < 4; ++n2) {
                        const int ntg = pp*8 + nh*4 + n2;
                        float2 bf = w3L[(ntg*8 + kt)*32 + lane];
                        mma8(c3[0][n2], af[0][kt], bf);
                        mma8(c3[1][n2], af[1][kt], bf);
                    }
                }
                #pragma unroll
                for (int mm = 0; mm < 2; ++mm) {
                    float P[4][2];
                    #pragma unroll
                    for (int n2 = 0; n2 < 4; ++n2) {
                        P[n2][0] = fmaxf(c3[mm][n2][0], c3[mm][n2][2]);
                        P[n2][1] = fmaxf(c3[mm][n2][1], c3[mm][n2][3]);
                    }
                    float e0 = g0 ? P[0][0] : P[1][0];
                    float e1 = g0 ? P[0][1] : P[1][1];
                    float e2 = g0 ? P[2][0] : P[3][0];
                    float e3 = g0 ? P[2][1] : P[3][1];
                    float K0v0 = g0 ? P[1][0] : P[0][0];
                    float K0v1 = g0 ? P[1][1] : P[0][1];
                    float K1v0 = g0 ? P[3][0] : P[2][0];
                    float K1v1 = g0 ? P[3][1] : P[2][1];
                    K0v0 = fmaxf(K0v0, __shfl_xor_sync(0xffffffffu, e0, 4));
                    K0v1 = fmaxf(K0v1, __shfl_xor_sync(0xffffffffu, e1, 4));
                    K1v0 = fmaxf(K1v0, __shfl_xor_sync(0xffffffffu, e2, 4));
                    K1v1 = fmaxf(K1v1, __shfl_xor_sync(0xffffffffu, e3, 4));
                    float f0  = g1 ? K0v0 : K1v0;
                    float f1  = g1 ? K0v1 : K1v1;
                    float Rv0 = g1 ? K1v0 : K0v0;
                    float Rv1 = g1 ? K1v1 : K0v1;
                    Rv0 = fmaxf(Rv0, __shfl_xor_sync(0xffffffffu, f0, 8));
                    Rv1 = fmaxf(Rv1, __shfl_xor_sync(0xffffffffu, f1, 8));
                    Rv0 = fmaxf(Rv0, __shfl_xor_sync(0xffffffffu, Rv0, 16));
                    Rv1 = fmaxf(Rv1, __shfl_xor_sync(0xffffffffu, Rv1, 16));
                    if (g2 == nh) {
                        const int col = (pp*8 + nh*4 + (g & 3))*8 + 2*tg;
                        float2 b3v = *(float2*)&sb3[col];
                        *(float2*)&out[(mm ? rbB : rbA) + col] =
                            make_float2(Rv0 + b3v.x, Rv1 + b3v.y);
                    }
                }
            }
        }
    }
}

extern "C" void kernel_launch(void* const* d_in, const int* in_sizes, int n_in,
                              void* d_out, int out_size)
{
    const float* windows = (const float*)d_in[0];
    const float* W1 = (const float*)d_in[1];
    const float* b1 = (const float*)d_in[2];
    const float* W2 = (const float*)d_in[3];
    const float* b2 = (const float*)d_in[4];
    const float* W3 = (const float*)d_in[5];
    const float* b3 = (const float*)d_in[6];
    float* out = (float*)d_out;

    cudaFuncSetAttribute(mini_embedding_mma,
                         cudaFuncAttributeMaxDynamicSharedMemorySize, SMEM_TOTAL);

    const int M = in_sizes[0] / (128 * 3);
    mini_embedding_mma<<<M, NT, SMEM_TOTAL>>>(windows, W1, b1, W2, b2, W3, b3, out);
}